// round 9
// baseline (speedup 1.0000x reference)
#include <cuda_runtime.h>
#include <cuda_bf16.h>
#include <math.h>
#include <stdint.h>

// ---------------- problem constants ----------------
#define BATCH   2
#define LSEQ    2048
#define DM      1024
#define DI      2048
#define DS      16
#define DC      4
#define RANK    64
#define GDIM    96
#define GP      128
#define BL      (BATCH*LSEQ)  // 4096
#define SPLITK  4
#define NCH     16
#define CHL     (LSEQ/NCH)    // 128

// ---------------- scratch ----------------
__device__ __nv_bfloat16 g_xn_bf  [(size_t)BL*DM];
__device__ __nv_bfloat16 g_xz_bf  [(size_t)BL*2*DI];
__device__ __nv_bfloat16 g_u_bf   [(size_t)BL*DI];
__device__ float         g_part   [(size_t)SPLITK*BL*GP];
__device__ float         g_xdbl   [(size_t)BL*GP];
__device__ __nv_bfloat16 g_dt_bf  [(size_t)BL*RANK];
__device__ __nv_bfloat16 g_del_bf [(size_t)BL*DI];
__device__ float         g_w1     [(size_t)BL*DI];
__device__ __nv_bfloat16 g_yg_bf  [(size_t)BL*DI];
__device__ float         g_S      [(size_t)BATCH*NCH*DI*DS];
__device__ float         g_H0     [(size_t)BATCH*NCH*DI*DS];
__device__ float         g_dsum   [(size_t)BATCH*NCH*DI];
__device__ __nv_bfloat16 g_wt_in  [(size_t)(2*DI)*DM];
__device__ __nv_bfloat16 g_wt_out [(size_t)DM*DI];
__device__ __nv_bfloat16 g_wt_xp  [(size_t)GP*DI];
__device__ __nv_bfloat16 g_wt_dt  [(size_t)DI*RANK];

// ---------------- helpers ----------------
__device__ __forceinline__ uint32_t smem_u32(const void* p) {
    uint32_t a;
    asm("{ .reg .u64 t; cvta.to.shared.u64 t, %1; cvt.u32.u64 %0, t; }" : "=r"(a) : "l"(p));
    return a;
}
__device__ __forceinline__ void cp16(uint32_t dst, const void* src) {
    asm volatile("cp.async.cg.shared.global [%0], [%1], 16;" :: "r"(dst), "l"(src));
}
#define CP_COMMIT() asm volatile("cp.async.commit_group;")
#define CP_WAIT1()  asm volatile("cp.async.wait_group 1;")

__device__ __forceinline__ void mma_bf16(float* c, const uint32_t* a, const uint32_t* b) {
    asm volatile(
        "mma.sync.aligned.m16n8k16.row.col.f32.bf16.bf16.f32 "
        "{%0,%1,%2,%3}, {%4,%5,%6,%7}, {%8,%9}, {%0,%1,%2,%3};"
        : "+f"(c[0]), "+f"(c[1]), "+f"(c[2]), "+f"(c[3])
        : "r"(a[0]), "r"(a[1]), "r"(a[2]), "r"(a[3]), "r"(b[0]), "r"(b[1]));
}
#define LDSM4(r0, r1, r2, r3, addr) \
    asm volatile("ldmatrix.sync.aligned.m8n8.x4.shared.b16 {%0,%1,%2,%3}, [%4];" \
        : "=r"(r0), "=r"(r1), "=r"(r2), "=r"(r3) : "r"(addr))

__device__ __forceinline__ float softplus_f(float t) {
    return (t > 20.f) ? t : __logf(1.f + __expf(t));
}
__device__ __forceinline__ void powers16(float w, float* pw) {
    const float w2 = w * w, w4 = w2 * w2, w8 = w4 * w4;
    pw[0]  = w;        pw[1]  = w2;       pw[2]  = w2 * w;   pw[3]  = w4;
    pw[4]  = w4 * w;   pw[5]  = w4 * w2;  pw[6]  = w4 * pw[2]; pw[7] = w8;
    pw[8]  = w8 * w;   pw[9]  = w8 * w2;  pw[10] = w8 * pw[2]; pw[11] = w8 * w4;
    pw[12] = w8 * pw[4]; pw[13] = w8 * pw[5]; pw[14] = w8 * pw[6]; pw[15] = w8 * w8;
}

// ---------------- prep: all weight transposes + layernorm, one launch -------
__device__ __forceinline__ void transpose64(const float* in, __nv_bfloat16* out,
                                            int K, int Nsrc, int Nout,
                                            int kb, int nb, int tx, int ty,
                                            float (*t)[33]) {
#pragma unroll
    for (int r = ty; r < 64; r += 8) {
        const int n = nb + tx;
        t[r][tx] = (n < Nsrc) ? in[(size_t)(kb + r) * Nsrc + n] : 0.f;
    }
    __syncthreads();
#pragma unroll
    for (int j = ty; j < 32; j += 8) {
        const int n = nb + j;
        if (n < Nout) {
            const __nv_bfloat162 v = __floats2bfloat162_rn(t[tx * 2][j], t[tx * 2 + 1][j]);
            *(__nv_bfloat162*)(out + (size_t)n * K + kb + tx * 2) = v;
        }
    }
}

__global__ void prep_kernel(const float* __restrict__ x,
                            const float* __restrict__ gamma,
                            const float* __restrict__ beta,
                            const float* __restrict__ Win,
                            const float* __restrict__ Wout,
                            const float* __restrict__ Wxp,
                            const float* __restrict__ Wdt,
                            __nv_bfloat16* __restrict__ xn,
                            __nv_bfloat16* __restrict__ wtin,
                            __nv_bfloat16* __restrict__ wtout,
                            __nv_bfloat16* __restrict__ wtxp,
                            __nv_bfloat16* __restrict__ wtdt) {
    __shared__ float t[64][33];
    const int tx = threadIdx.x, ty = threadIdx.y;
    int b = blockIdx.x;
    if (b < 2048) {
        transpose64(Win, wtin, DM, 2 * DI, 2 * DI, (b & 15) * 64, (b >> 4) * 32, tx, ty, t);
    } else if (b < 3072) {
        b -= 2048;
        transpose64(Wout, wtout, DI, DM, DM, (b & 31) * 64, (b >> 5) * 32, tx, ty, t);
    } else if (b < 3200) {
        b -= 3072;
        transpose64(Wxp, wtxp, DI, GDIM, GP, (b & 31) * 64, (b >> 5) * 32, tx, ty, t);
    } else if (b < 3264) {
        b -= 3200;
        transpose64(Wdt, wtdt, RANK, DI, DI, 0, b * 32, tx, ty, t);
    } else {
        const int row = b - 3264;
        const int tid = ty * 32 + tx;
        const float4 v = ((const float4*)(x + (size_t)row * DM))[tid];
        float s  = v.x + v.y + v.z + v.w;
        float s2 = v.x * v.x + v.y * v.y + v.z * v.z + v.w * v.w;
#pragma unroll
        for (int o = 16; o > 0; o >>= 1) {
            s  += __shfl_xor_sync(0xffffffffu, s,  o);
            s2 += __shfl_xor_sync(0xffffffffu, s2, o);
        }
        if ((tid & 31) == 0) { t[0][tid >> 5] = s; t[1][tid >> 5] = s2; }
        __syncthreads();
        s = 0.f; s2 = 0.f;
#pragma unroll
        for (int i = 0; i < 8; i++) { s += t[0][i]; s2 += t[1][i]; }
        const float mean = s * (1.f / DM);
        const float var  = s2 * (1.f / DM) - mean * mean;
        const float rstd = rsqrtf(var + 1e-5f);
        const float4 gm = ((const float4*)gamma)[tid];
        const float4 bt = ((const float4*)beta)[tid];
        __nv_bfloat16* orow = xn + (size_t)row * DM + tid * 4;
        *(__nv_bfloat162*)(orow) =
            __floats2bfloat162_rn((v.x - mean) * rstd * gm.x + bt.x,
                                  (v.y - mean) * rstd * gm.y + bt.y);
        *(__nv_bfloat162*)(orow + 2) =
            __floats2bfloat162_rn((v.z - mean) * rstd * gm.z + bt.z,
                                  (v.w - mean) * rstd * gm.w + bt.w);
    }
}

// ---------------- conv + silu (8 channels/thread, vectorized) ----------------
__global__ void conv_silu_kernel(const __nv_bfloat16* __restrict__ xz,
                                 const float* __restrict__ w,
                                 const float* __restrict__ bias,
                                 __nv_bfloat16* __restrict__ ubf) {
    const int idx = blockIdx.x * blockDim.x + threadIdx.x;  // BL*DI/8
    const int dg = idx & 255;
    const int bl = idx >> 8;
    const int l  = bl & (LSEQ - 1);
    const int d0 = dg << 3;

    float acc[8];
    {
        const float4 b0 = *(const float4*)(bias + d0);
        const float4 b1 = *(const float4*)(bias + d0 + 4);
        acc[0] = b0.x; acc[1] = b0.y; acc[2] = b0.z; acc[3] = b0.w;
        acc[4] = b1.x; acc[5] = b1.y; acc[6] = b1.z; acc[7] = b1.w;
    }
    float wv[4][8];
#pragma unroll
    for (int k = 0; k < 8; k++) {
        const float4 wk = *(const float4*)(w + (d0 + k) * 4);
        wv[0][k] = wk.x; wv[1][k] = wk.y; wv[2][k] = wk.z; wv[3][k] = wk.w;
    }
#pragma unroll
    for (int j = 0; j < DC; j++) {
        const int lj = l - 3 + j;
        if (lj >= 0) {
            const uint4 q = *(const uint4*)(xz + (size_t)(bl - 3 + j) * (2 * DI) + d0);
            const __nv_bfloat162* h = (const __nv_bfloat162*)&q;
#pragma unroll
            for (int k2 = 0; k2 < 4; k2++) {
                const float2 f = __bfloat1622float2(h[k2]);
                acc[k2 * 2]     = fmaf(wv[j][k2 * 2],     f.x, acc[k2 * 2]);
                acc[k2 * 2 + 1] = fmaf(wv[j][k2 * 2 + 1], f.y, acc[k2 * 2 + 1]);
            }
        }
    }
    uint4 oq;
    __nv_bfloat162* oh = (__nv_bfloat162*)&oq;
#pragma unroll
    for (int k2 = 0; k2 < 4; k2++) {
        const float a0 = acc[k2 * 2],     s0 = a0 / (1.f + __expf(-a0));
        const float a1 = acc[k2 * 2 + 1], s1 = a1 / (1.f + __expf(-a1));
        oh[k2] = __floats2bfloat162_rn(s0, s1);
    }
    *(uint4*)(ubf + (size_t)bl * DI + d0) = oq;
}

// ---------------- persistent bf16 mma.sync GEMM with ldmatrix ----------------
// C = A[M,K] @ Bt[N,K]^T, tiles 128x128, CTA processes `ntiles` tiles.
// tile id = blockIdx.x + t*gridDim.x ; bx = tile & (2^lgx - 1), by = tile >> lgx.
// EPI: 0 none | 1 softplus(acc+E[col]) -> bf16 C + fp32 W1=exp(sp*A1[col]) | 2 acc+E
template <int EPI, bool OBF>
__global__ __launch_bounds__(256, 2)
void mma_gemm_kernel(const __nv_bfloat16* __restrict__ A,
                     const __nv_bfloat16* __restrict__ Bt,
                     void* __restrict__ Cv,
                     int lda, int ldb, int ldc,
                     const float* __restrict__ E,
                     const float* __restrict__ Alog,
                     float* __restrict__ W1,
                     int Kloc, size_t partStride,
                     int lgK, int lgx, int ntiles) {
    constexpr int STAGE_BYTES = 2 * 128 * 128;
    constexpr int STAGES = 3;

    extern __shared__ __align__(128) char smem[];
    const uint32_t smem_b = smem_u32(smem);

    const int tid  = threadIdx.x;
    const int wid  = tid >> 5;
    const int lane = tid & 31;
    const int g    = lane >> 2;
    const int t    = lane & 3;
    const int rl   = lane & 7;
    const int l3   = (lane >> 3) & 1;
    const int l4   = lane >> 4;

    const int warpRow = wid & 1;
    const int warpCol = wid >> 1;
    const int kbase   = blockIdx.z * Kloc;
    const int nchMask = (1 << lgK) - 1;
    const int tcTot   = ntiles << lgK;
    const int bxMask  = (1 << lgx) - 1;

    float acc[4][4][4];
#pragma unroll
    for (int i = 0; i < 4; i++)
#pragma unroll
        for (int j = 0; j < 4; j++)
#pragma unroll
            for (int q = 0; q < 4; q++) acc[i][j][q] = 0.f;

    auto load_stage = [&](int gc, int s) {
        if (gc < tcTot) {
            const int tile = blockIdx.x + (gc >> lgK) * gridDim.x;
            const int cb = (tile & bxMask) << 7;
            const int rb = (tile >> lgx) << 7;
            const int kc = gc & nchMask;
            const uint32_t base = smem_b + (uint32_t)s * STAGE_BYTES;
            const int rw = wid * 4 + (lane >> 3);
            const int un = lane & 7;
#pragma unroll
            for (int it = 0; it < 4; it++) {
                const int r = it * 32 + rw;
                const uint32_t sw = (uint32_t)((un ^ (r & 7)) << 4);
                cp16(base + (uint32_t)r * 128 + sw,
                     A + (size_t)(rb + r) * lda + kbase + kc * 64 + un * 8);
                cp16(base + 16384u + (uint32_t)r * 128 + sw,
                     Bt + (size_t)(cb + r) * ldb + kbase + kc * 64 + un * 8);
            }
        }
        CP_COMMIT();
    };

    uint32_t rowOffA[4], colOffB[2];
#pragma unroll
    for (int mt = 0; mt < 4; mt++)
        rowOffA[mt] = (uint32_t)(warpRow * 64 + mt * 16 + l3 * 8 + rl) * 128;
#pragma unroll
    for (int n2 = 0; n2 < 2; n2++)
        colOffB[n2] = 16384u + (uint32_t)(warpCol * 32 + n2 * 16 + l4 * 8 + rl) * 128;

    load_stage(0, 0);
    load_stage(1, 1);

    int sidx = 0;
    for (int gc = 0; gc < tcTot; gc++) {
        CP_WAIT1();
        __syncthreads();
        int snext = sidx + 2; if (snext >= STAGES) snext -= STAGES;
        load_stage(gc + 2, snext);

        const uint32_t st = smem_b + (uint32_t)sidx * STAGE_BYTES;

#pragma unroll
        for (int ks = 0; ks < 4; ks++) {
            const uint32_t offA = (uint32_t)(((ks * 2 + l4) ^ rl) << 4);
            const uint32_t offB = (uint32_t)(((ks * 2 + l3) ^ rl) << 4);
            uint32_t afr[4][4], bfr[4][2];
#pragma unroll
            for (int mt = 0; mt < 4; mt++)
                LDSM4(afr[mt][0], afr[mt][1], afr[mt][2], afr[mt][3],
                      st + rowOffA[mt] + offA);
#pragma unroll
            for (int n2 = 0; n2 < 2; n2++)
                LDSM4(bfr[2 * n2][0], bfr[2 * n2][1], bfr[2 * n2 + 1][0], bfr[2 * n2 + 1][1],
                      st + colOffB[n2] + offB);
#pragma unroll
            for (int mt = 0; mt < 4; mt++)
#pragma unroll
                for (int nt = 0; nt < 4; nt++)
                    mma_bf16(acc[mt][nt], afr[mt], bfr[nt]);
        }

        if (((gc + 1) & nchMask) == 0) {
            // ---------------- epilogue for completed tile ----------------
            const int tile = blockIdx.x + (gc >> lgK) * gridDim.x;
            const int cb = (tile & bxMask) << 7;
            const int rb = (tile >> lgx) << 7;
            const int rW = rb + warpRow * 64;
            const int cW = cb + warpCol * 32;

            float av[4][2];
            if (EPI == 1) {
#pragma unroll
                for (int nt = 0; nt < 4; nt++) {
                    const int c0 = cW + nt * 8 + 2 * t;
                    av[nt][0] = -__expf(Alog[c0 * DS]);
                    av[nt][1] = -__expf(Alog[(c0 + 1) * DS]);
                }
            }
#pragma unroll
            for (int mt = 0; mt < 4; mt++) {
#pragma unroll
                for (int nt = 0; nt < 4; nt++) {
                    const int r0 = rW + mt * 16 + g;
                    const int r1 = r0 + 8;
                    const int c0 = cW + nt * 8 + 2 * t;
                    float v0 = acc[mt][nt][0], v1 = acc[mt][nt][1];
                    float v2 = acc[mt][nt][2], v3 = acc[mt][nt][3];
                    acc[mt][nt][0] = 0.f; acc[mt][nt][1] = 0.f;
                    acc[mt][nt][2] = 0.f; acc[mt][nt][3] = 0.f;
                    if (EPI == 1) {
                        const float b0 = E[c0], b1 = E[c0 + 1];
                        v0 = softplus_f(v0 + b0);
                        v1 = softplus_f(v1 + b1);
                        v2 = softplus_f(v2 + b0);
                        v3 = softplus_f(v3 + b1);
                        *(float2*)(W1 + (size_t)r0 * ldc + c0) =
                            make_float2(__expf(v0 * av[nt][0]), __expf(v1 * av[nt][1]));
                        *(float2*)(W1 + (size_t)r1 * ldc + c0) =
                            make_float2(__expf(v2 * av[nt][0]), __expf(v3 * av[nt][1]));
                    } else if (EPI == 2) {
                        const float2 e0 = *(const float2*)(E + (size_t)r0 * ldc + c0);
                        const float2 e1 = *(const float2*)(E + (size_t)r1 * ldc + c0);
                        v0 += e0.x; v1 += e0.y; v2 += e1.x; v3 += e1.y;
                    }
                    if (OBF) {
                        __nv_bfloat16* C = (__nv_bfloat16*)Cv + (size_t)blockIdx.z * partStride;
                        *(__nv_bfloat162*)(C + (size_t)r0 * ldc + c0) = __floats2bfloat162_rn(v0, v1);
                        *(__nv_bfloat162*)(C + (size_t)r1 * ldc + c0) = __floats2bfloat162_rn(v2, v3);
                    } else {
                        float* C = (float*)Cv + (size_t)blockIdx.z * partStride;
                        *(float2*)(C + (size_t)r0 * ldc + c0) = make_float2(v0, v1);
                        *(float2*)(C + (size_t)r1 * ldc + c0) = make_float2(v2, v3);
                    }
                }
            }
        }
        sidx++; if (sidx >= STAGES) sidx -= STAGES;
    }
}

// ---------------- split-K reduce (float4) + dt->bf16 ----------------
__global__ void reduce_xdbl_kernel(const float* __restrict__ part,
                                   float* __restrict__ xdbl,
                                   __nv_bfloat16* __restrict__ dtbf) {
    const int i4 = blockIdx.x * blockDim.x + threadIdx.x;    // BL*GP/4
    const size_t S4 = (size_t)BL * GP / 4;
    const float4* p4 = (const float4*)part;
    const float4 a = p4[i4], b = p4[i4 + S4], c = p4[i4 + 2 * S4], d = p4[i4 + 3 * S4];
    float4 s;
    s.x = a.x + b.x + c.x + d.x;
    s.y = a.y + b.y + c.y + d.y;
    s.z = a.z + b.z + c.z + d.z;
    s.w = a.w + b.w + c.w + d.w;
    ((float4*)xdbl)[i4] = s;
    const int col = (i4 << 2) & (GP - 1);
    if (col < RANK) {
        const int row = i4 >> 5;
        __nv_bfloat16* dp = dtbf + (size_t)row * RANK + col;
        *(__nv_bfloat162*)(dp)     = __floats2bfloat162_rn(s.x, s.y);
        *(__nv_bfloat162*)(dp + 2) = __floats2bfloat162_rn(s.z, s.w);
    }
}

// ---------------- scan pass A ----------------
__global__ void scanA_kernel(const __nv_bfloat16* __restrict__ delta,
                             const float* __restrict__ w1,
                             const __nv_bfloat16* __restrict__ u,
                             const float* __restrict__ xdbl,
                             const float* __restrict__ A_log,
                             float* __restrict__ S, float* __restrict__ dsum) {
    __shared__ float Bs[CHL * DS];
    const int tid = threadIdx.x;
    const int d = blockIdx.x * 128 + tid;
    const int c = blockIdx.y, b = blockIdx.z;
    const int l0 = c * CHL;

    const float4* xd4 = (const float4*)xdbl;
    for (int i = tid; i < CHL * 4; i += 128) {
        const int l = i >> 2, q = i & 3;
        ((float4*)Bs)[l * 4 + q] = xd4[((size_t)(b * LSEQ + l0 + l)) * 32 + 16 + q];
    }

    float Av[DS];
#pragma unroll
    for (int n = 0; n < DS; n++) Av[n] = -__expf(A_log[d * DS + n]);
    bool structured = (Av[0] < 0.f);
#pragma unroll
    for (int n = 1; n < DS; n++)
        structured = structured && (fabsf(Av[n] - (n + 1) * Av[0]) <= 1e-5f * fabsf(Av[n]));
    __syncthreads();

    float h[DS];
#pragma unroll
    for (int n = 0; n < DS; n++) h[n] = 0.f;
    float ds = 0.f;

    size_t p = ((size_t)(b * LSEQ + l0)) * DI + d;
    for (int l = 0; l < CHL; l++, p += DI) {
        const float dv = __bfloat162float(delta[p]);
        const float uv = __bfloat162float(u[p]);
        ds += dv;
        const float cv = dv * uv;
        float pw[DS];
        if (structured) {
            powers16(w1[p], pw);
        } else {
#pragma unroll
            for (int n = 0; n < DS; n++) pw[n] = __expf(dv * Av[n]);
        }
#pragma unroll
        for (int n = 0; n < DS; n++)
            h[n] = fmaf(pw[n], h[n], cv * Bs[l * DS + n]);
    }

    const size_t o = ((size_t)((b * NCH + c) * DI) + d) * DS;
#pragma unroll
    for (int n = 0; n < DS; n++) S[o + n] = h[n];
    dsum[(size_t)(b * NCH + c) * DI + d] = ds;
}

// ---------------- scan pass B ----------------
__global__ void scanB_kernel(const float* __restrict__ S,
                             const float* __restrict__ dsum,
                             const float* __restrict__ A_log,
                             float* __restrict__ H0) {
    const int idx = blockIdx.x * blockDim.x + threadIdx.x;
    const int n = idx & 15;
    const int d = (idx >> 4) & (DI - 1);
    const int b = idx >> 15;
    const float Av = -__expf(A_log[d * DS + n]);
    float h = 0.f;
#pragma unroll
    for (int c = 0; c < NCH; c++) {
        const size_t o = ((size_t)((b * NCH + c) * DI) + d) * DS + n;
        H0[o] = h;
        const float P = __expf(dsum[(size_t)(b * NCH + c) * DI + d] * Av);
        h = fmaf(P, h, S[o]);
    }
}

// ---------------- scan pass C ----------------
__global__ void scanC_kernel(const __nv_bfloat16* __restrict__ delta,
                             const float* __restrict__ w1,
                             const __nv_bfloat16* __restrict__ u,
                             const float* __restrict__ xdbl,
                             const __nv_bfloat16* __restrict__ xz,
                             const float* __restrict__ A_log,
                             const float* __restrict__ Dskip,
                             const float* __restrict__ H0,
                             __nv_bfloat16* __restrict__ yg) {
    __shared__ float Bs[CHL * DS];
    __shared__ float Cs[CHL * DS];
    const int tid = threadIdx.x;
    const int d = blockIdx.x * 128 + tid;
    const int c = blockIdx.y, b = blockIdx.z;
    const int l0 = c * CHL;

    const float4* xd4 = (const float4*)xdbl;
    for (int i = tid; i < CHL * 4; i += 128) {
        const int l = i >> 2, q = i & 3;
        const size_t row = ((size_t)(b * LSEQ + l0 + l)) * 32;
        ((float4*)Bs)[l * 4 + q] = xd4[row + 16 + q];
        ((float4*)Cs)[l * 4 + q] = xd4[row + 20 + q];
    }

    float Av[DS];
#pragma unroll
    for (int n = 0; n < DS; n++) Av[n] = -__expf(A_log[d * DS + n]);
    bool structured = (Av[0] < 0.f);
#pragma unroll
    for (int n = 1; n < DS; n++)
        structured = structured && (fabsf(Av[n] - (n + 1) * Av[0]) <= 1e-5f * fabsf(Av[n]));
    const float dsk = Dskip[d];
    __syncthreads();

    float h[DS];
    const size_t ho = ((size_t)((b * NCH + c) * DI) + d) * DS;
#pragma unroll
    for (int n = 0; n < DS; n++) h[n] = H0[ho + n];

    size_t p = ((size_t)(b * LSEQ + l0)) * DI + d;
    for (int l = 0; l < CHL; l++, p += DI) {
        const float dv = __bfloat162float(delta[p]);
        const float uv = __bfloat162float(u[p]);
        const float zv = __bfloat162float(xz[((size_t)(b * LSEQ + l0 + l)) * (2 * DI) + DI + d]);
        const float cv = dv * uv;
        float pw[DS];
        if (structured) {
            powers16(w1[p], pw);
        } else {
#pragma unroll
            for (int n = 0; n < DS; n++) pw[n] = __expf(dv * Av[n]);
        }
        float y0 = 0.f, y1 = 0.f, y2 = 0.f, y3 = 0.f;
#pragma unroll
        for (int n = 0; n < DS; n += 4) {
            h[n]     = fmaf(pw[n],     h[n],     cv * Bs[l * DS + n]);
            h[n + 1] = fmaf(pw[n + 1], h[n + 1], cv * Bs[l * DS + n + 1]);
            h[n + 2] = fmaf(pw[n + 2], h[n + 2], cv * Bs[l * DS + n + 2]);
            h[n + 3] = fmaf(pw[n + 3], h[n + 3], cv * Bs[l * DS + n + 3]);
            y0 = fmaf(h[n],     Cs[l * DS + n],     y0);
            y1 = fmaf(h[n + 1], Cs[l * DS + n + 1], y1);
            y2 = fmaf(h[n + 2], Cs[l * DS + n + 2], y2);
            y3 = fmaf(h[n + 3], Cs[l * DS + n + 3], y3);
        }
        const float y = (y0 + y1) + (y2 + y3) + uv * dsk;
        const float sig = 1.f / (1.f + __expf(-zv));
        yg[p] = __float2bfloat16(y * (zv * sig));
    }
}

// ---------------- launch ----------------
extern "C" void kernel_launch(void* const* d_in, const int* in_sizes, int n_in,
                              void* d_out, int out_size) {
    const float* x       = (const float*)d_in[0];
    const float* ln_g    = (const float*)d_in[1];
    const float* ln_b    = (const float*)d_in[2];
    const float* W_in    = (const float*)d_in[3];
    const float* conv_w  = (const float*)d_in[4];
    const float* conv_b  = (const float*)d_in[5];
    const float* W_xproj = (const float*)d_in[6];
    const float* W_dt    = (const float*)d_in[7];
    const float* b_dt    = (const float*)d_in[8];
    const float* A_log   = (const float*)d_in[9];
    const float* D_skip  = (const float*)d_in[10];
    const float* W_out   = (const float*)d_in[11];
    float* out = (float*)d_out;

    __nv_bfloat16 *xn, *xzbf, *ubf, *dtbf, *delbf, *yg, *wtin, *wtout, *wtxp, *wtdt;
    float *part, *xdbl, *w1b, *Sb, *H0b, *dsumb;
    cudaGetSymbolAddress((void**)&xn,    g_xn_bf);
    cudaGetSymbolAddress((void**)&xzbf,  g_xz_bf);
    cudaGetSymbolAddress((void**)&ubf,   g_u_bf);
    cudaGetSymbolAddress((void**)&part,  g_part);
    cudaGetSymbolAddress((void**)&xdbl,  g_xdbl);
    cudaGetSymbolAddress((void**)&dtbf,  g_dt_bf);
    cudaGetSymbolAddress((void**)&delbf, g_del_bf);
    cudaGetSymbolAddress((void**)&w1b,   g_w1);
    cudaGetSymbolAddress((void**)&yg,    g_yg_bf);
    cudaGetSymbolAddress((void**)&Sb,    g_S);
    cudaGetSymbolAddress((void**)&H0b,   g_H0);
    cudaGetSymbolAddress((void**)&dsumb, g_dsum);
    cudaGetSymbolAddress((void**)&wtin,  g_wt_in);
    cudaGetSymbolAddress((void**)&wtout, g_wt_out);
    cudaGetSymbolAddress((void**)&wtxp,  g_wt_xp);
    cudaGetSymbolAddress((void**)&wtdt,  g_wt_dt);

    const int smemBytes = 3 * 2 * 128 * 128;   // 98304
    cudaFuncSetAttribute(mma_gemm_kernel<0, true>,  cudaFuncAttributeMaxDynamicSharedMemorySize, smemBytes);
    cudaFuncSetAttribute(mma_gemm_kernel<0, false>, cudaFuncAttributeMaxDynamicSharedMemorySize, smemBytes);
    cudaFuncSetAttribute(mma_gemm_kernel<1, true>,  cudaFuncAttributeMaxDynamicSharedMemorySize, smemBytes);
    cudaFuncSetAttribute(mma_gemm_kernel<2, false>, cudaFuncAttributeMaxDynamicSharedMemorySize, smemBytes);

    // 1) prep
    prep_kernel<<<3264 + BL, dim3(32, 8)>>>(x, ln_g, ln_b, W_in, W_out, W_xproj, W_dt,
                                            xn, wtin, wtout, wtxp, wtdt);
    // 2) xz = xn @ W_in -> bf16 ; tiles 32x32=1024, grid 512 x 2 tiles
    mma_gemm_kernel<0, true><<<dim3(512, 1, 1), 256, smemBytes>>>(
        xn, wtin, xzbf, DM, DM, 2 * DI, nullptr, nullptr, nullptr, DM, 0, 4, 5, 2);
    // 3) conv + silu
    conv_silu_kernel<<<((size_t)BL * DI / 8) / 256, 256>>>(xzbf, conv_w, conv_b, ubf);
    // 4) x_dbl partials, split-K 4 ; tiles 1x32 per split  (PROFILED)
    mma_gemm_kernel<0, false><<<dim3(32, 1, SPLITK), 256, smemBytes>>>(
        ubf, wtxp, part, DI, DI, GP, nullptr, nullptr, nullptr, DI / SPLITK,
        (size_t)BL * GP, 3, 0, 1);
    // 5) reduce
    reduce_xdbl_kernel<<<(BL * GP / 4) / 256, 256>>>(part, xdbl, dtbf);
    // 6) delta = softplus(dt @ W_dt + b_dt) -> bf16 + w1 ; tiles 16x32=512, grid 256 x 2
    mma_gemm_kernel<1, true><<<dim3(256, 1, 1), 256, smemBytes>>>(
        dtbf, wtdt, delbf, RANK, RANK, DI, b_dt, A_log, w1b, RANK, 0, 0, 4, 2);
    // 7-9) chunked selective scan
    scanA_kernel<<<dim3(DI / 128, NCH, BATCH), 128>>>(delbf, w1b, ubf, xdbl, A_log, Sb, dsumb);
    scanB_kernel<<<(BATCH * DI * DS) / 256, 256>>>(Sb, dsumb, A_log, H0b);
    scanC_kernel<<<dim3(DI / 128, NCH, BATCH), 128>>>(delbf, w1b, ubf, xdbl, xzbf,
                                                      A_log, D_skip, H0b, yg);
    // 10) out = x + yg @ W_out ; tiles 8x32=256, grid 256 x 1
    mma_gemm_kernel<2, false><<<dim3(256, 1, 1), 256, smemBytes>>>(
        yg, wtout, out, DI, DI, DM, x, nullptr, nullptr, DI, 0, 5, 3, 1);
}

// round 10
// speedup vs baseline: 1.0119x; 1.0119x over previous
#include <cuda_runtime.h>
#include <cuda_bf16.h>
#include <math.h>
#include <stdint.h>

// ---------------- problem constants ----------------
#define BATCH   2
#define LSEQ    2048
#define DM      1024
#define DI      2048
#define DS      16
#define DC      4
#define RANK    64
#define GDIM    96
#define GP      128
#define BL      (BATCH*LSEQ)  // 4096
#define SPLITK  4
#define NCH     32
#define CHL     (LSEQ/NCH)    // 64

// ---------------- scratch ----------------
__device__ __nv_bfloat16 g_xn_bf  [(size_t)BL*DM];
__device__ __nv_bfloat16 g_xz_bf  [(size_t)BL*2*DI];
__device__ __nv_bfloat16 g_u_bf   [(size_t)BL*DI];
__device__ float         g_part   [(size_t)SPLITK*BL*GP];
__device__ float         g_xdbl   [(size_t)BL*GP];
__device__ __nv_bfloat16 g_dt_bf  [(size_t)BL*RANK];
__device__ __nv_bfloat16 g_del_bf [(size_t)BL*DI];
__device__ __nv_bfloat16 g_yg_bf  [(size_t)BL*DI];
__device__ float         g_S      [(size_t)BATCH*NCH*DI*DS];
__device__ float         g_H0     [(size_t)BATCH*NCH*DI*DS];
__device__ float         g_dsum   [(size_t)BATCH*NCH*DI];
__device__ __nv_bfloat16 g_wt_in  [(size_t)(2*DI)*DM];
__device__ __nv_bfloat16 g_wt_out [(size_t)DM*DI];
__device__ __nv_bfloat16 g_wt_xp  [(size_t)GP*DI];
__device__ __nv_bfloat16 g_wt_dt  [(size_t)DI*RANK];

// ---------------- helpers ----------------
__device__ __forceinline__ uint32_t smem_u32(const void* p) {
    uint32_t a;
    asm("{ .reg .u64 t; cvta.to.shared.u64 t, %1; cvt.u32.u64 %0, t; }" : "=r"(a) : "l"(p));
    return a;
}
__device__ __forceinline__ void cp16(uint32_t dst, const void* src) {
    asm volatile("cp.async.cg.shared.global [%0], [%1], 16;" :: "r"(dst), "l"(src));
}
#define CP_COMMIT() asm volatile("cp.async.commit_group;")
#define CP_WAIT1()  asm volatile("cp.async.wait_group 1;")

__device__ __forceinline__ void mma_bf16(float* c, const uint32_t* a, const uint32_t* b) {
    asm volatile(
        "mma.sync.aligned.m16n8k16.row.col.f32.bf16.bf16.f32 "
        "{%0,%1,%2,%3}, {%4,%5,%6,%7}, {%8,%9}, {%0,%1,%2,%3};"
        : "+f"(c[0]), "+f"(c[1]), "+f"(c[2]), "+f"(c[3])
        : "r"(a[0]), "r"(a[1]), "r"(a[2]), "r"(a[3]), "r"(b[0]), "r"(b[1]));
}
#define LDSM4(r0, r1, r2, r3, addr) \
    asm volatile("ldmatrix.sync.aligned.m8n8.x4.shared.b16 {%0,%1,%2,%3}, [%4];" \
        : "=r"(r0), "=r"(r1), "=r"(r2), "=r"(r3) : "r"(addr))

__device__ __forceinline__ float softplus_f(float t) {
    return (t > 20.f) ? t : __logf(1.f + __expf(t));
}
__device__ __forceinline__ void powers16(float w, float* pw) {
    const float w2 = w * w, w4 = w2 * w2, w8 = w4 * w4;
    pw[0]  = w;        pw[1]  = w2;       pw[2]  = w2 * w;   pw[3]  = w4;
    pw[4]  = w4 * w;   pw[5]  = w4 * w2;  pw[6]  = w4 * pw[2]; pw[7] = w8;
    pw[8]  = w8 * w;   pw[9]  = w8 * w2;  pw[10] = w8 * pw[2]; pw[11] = w8 * w4;
    pw[12] = w8 * pw[4]; pw[13] = w8 * pw[5]; pw[14] = w8 * pw[6]; pw[15] = w8 * w8;
}

// ---------------- prep: all weight transposes + layernorm, one launch -------
__device__ __forceinline__ void transpose64(const float* in, __nv_bfloat16* out,
                                            int K, int Nsrc, int Nout,
                                            int kb, int nb, int tx, int ty,
                                            float (*t)[33]) {
#pragma unroll
    for (int r = ty; r < 64; r += 8) {
        const int n = nb + tx;
        t[r][tx] = (n < Nsrc) ? in[(size_t)(kb + r) * Nsrc + n] : 0.f;
    }
    __syncthreads();
#pragma unroll
    for (int j = ty; j < 32; j += 8) {
        const int n = nb + j;
        if (n < Nout) {
            const __nv_bfloat162 v = __floats2bfloat162_rn(t[tx * 2][j], t[tx * 2 + 1][j]);
            *(__nv_bfloat162*)(out + (size_t)n * K + kb + tx * 2) = v;
        }
    }
}

__global__ void prep_kernel(const float* __restrict__ x,
                            const float* __restrict__ gamma,
                            const float* __restrict__ beta,
                            const float* __restrict__ Win,
                            const float* __restrict__ Wout,
                            const float* __restrict__ Wxp,
                            const float* __restrict__ Wdt,
                            __nv_bfloat16* __restrict__ xn,
                            __nv_bfloat16* __restrict__ wtin,
                            __nv_bfloat16* __restrict__ wtout,
                            __nv_bfloat16* __restrict__ wtxp,
                            __nv_bfloat16* __restrict__ wtdt) {
    __shared__ float t[64][33];
    const int tx = threadIdx.x, ty = threadIdx.y;
    int b = blockIdx.x;
    if (b < 2048) {
        transpose64(Win, wtin, DM, 2 * DI, 2 * DI, (b & 15) * 64, (b >> 4) * 32, tx, ty, t);
    } else if (b < 3072) {
        b -= 2048;
        transpose64(Wout, wtout, DI, DM, DM, (b & 31) * 64, (b >> 5) * 32, tx, ty, t);
    } else if (b < 3200) {
        b -= 3072;
        transpose64(Wxp, wtxp, DI, GDIM, GP, (b & 31) * 64, (b >> 5) * 32, tx, ty, t);
    } else if (b < 3264) {
        b -= 3200;
        transpose64(Wdt, wtdt, RANK, DI, DI, 0, b * 32, tx, ty, t);
    } else {
        const int row = b - 3264;
        const int tid = ty * 32 + tx;
        const float4 v = ((const float4*)(x + (size_t)row * DM))[tid];
        float s  = v.x + v.y + v.z + v.w;
        float s2 = v.x * v.x + v.y * v.y + v.z * v.z + v.w * v.w;
#pragma unroll
        for (int o = 16; o > 0; o >>= 1) {
            s  += __shfl_xor_sync(0xffffffffu, s,  o);
            s2 += __shfl_xor_sync(0xffffffffu, s2, o);
        }
        if ((tid & 31) == 0) { t[0][tid >> 5] = s; t[1][tid >> 5] = s2; }
        __syncthreads();
        s = 0.f; s2 = 0.f;
#pragma unroll
        for (int i = 0; i < 8; i++) { s += t[0][i]; s2 += t[1][i]; }
        const float mean = s * (1.f / DM);
        const float var  = s2 * (1.f / DM) - mean * mean;
        const float rstd = rsqrtf(var + 1e-5f);
        const float4 gm = ((const float4*)gamma)[tid];
        const float4 bt = ((const float4*)beta)[tid];
        __nv_bfloat16* orow = xn + (size_t)row * DM + tid * 4;
        *(__nv_bfloat162*)(orow) =
            __floats2bfloat162_rn((v.x - mean) * rstd * gm.x + bt.x,
                                  (v.y - mean) * rstd * gm.y + bt.y);
        *(__nv_bfloat162*)(orow + 2) =
            __floats2bfloat162_rn((v.z - mean) * rstd * gm.z + bt.z,
                                  (v.w - mean) * rstd * gm.w + bt.w);
    }
}

// ---------------- conv + silu (8 channels/thread, vectorized) ----------------
__global__ void conv_silu_kernel(const __nv_bfloat16* __restrict__ xz,
                                 const float* __restrict__ w,
                                 const float* __restrict__ bias,
                                 __nv_bfloat16* __restrict__ ubf) {
    const int idx = blockIdx.x * blockDim.x + threadIdx.x;  // BL*DI/8
    const int dg = idx & 255;
    const int bl = idx >> 8;
    const int l  = bl & (LSEQ - 1);
    const int d0 = dg << 3;

    float acc[8];
    {
        const float4 b0 = *(const float4*)(bias + d0);
        const float4 b1 = *(const float4*)(bias + d0 + 4);
        acc[0] = b0.x; acc[1] = b0.y; acc[2] = b0.z; acc[3] = b0.w;
        acc[4] = b1.x; acc[5] = b1.y; acc[6] = b1.z; acc[7] = b1.w;
    }
    float wv[4][8];
#pragma unroll
    for (int k = 0; k < 8; k++) {
        const float4 wk = *(const float4*)(w + (d0 + k) * 4);
        wv[0][k] = wk.x; wv[1][k] = wk.y; wv[2][k] = wk.z; wv[3][k] = wk.w;
    }
#pragma unroll
    for (int j = 0; j < DC; j++) {
        const int lj = l - 3 + j;
        if (lj >= 0) {
            const uint4 q = *(const uint4*)(xz + (size_t)(bl - 3 + j) * (2 * DI) + d0);
            const __nv_bfloat162* h = (const __nv_bfloat162*)&q;
#pragma unroll
            for (int k2 = 0; k2 < 4; k2++) {
                const float2 f = __bfloat1622float2(h[k2]);
                acc[k2 * 2]     = fmaf(wv[j][k2 * 2],     f.x, acc[k2 * 2]);
                acc[k2 * 2 + 1] = fmaf(wv[j][k2 * 2 + 1], f.y, acc[k2 * 2 + 1]);
            }
        }
    }
    uint4 oq;
    __nv_bfloat162* oh = (__nv_bfloat162*)&oq;
#pragma unroll
    for (int k2 = 0; k2 < 4; k2++) {
        const float a0 = acc[k2 * 2],     s0 = a0 / (1.f + __expf(-a0));
        const float a1 = acc[k2 * 2 + 1], s1 = a1 / (1.f + __expf(-a1));
        oh[k2] = __floats2bfloat162_rn(s0, s1);
    }
    *(uint4*)(ubf + (size_t)bl * DI + d0) = oq;
}

// ---------------- bf16 mma.sync GEMM with ldmatrix (R8 proven version) ------
// C[M,N] = A[M,K] @ Bt[N,K]^T ; EPI: 0 none | 1 softplus(acc+E[col]) | 2 acc+E
template <int EPI, bool OBF>
__global__ __launch_bounds__(256, 2)
void mma_gemm_kernel(const __nv_bfloat16* __restrict__ A,
                     const __nv_bfloat16* __restrict__ Bt,
                     void* __restrict__ Cv, int M, int N,
                     int lda, int ldb, int ldc, const float* __restrict__ E,
                     int Kloc, size_t partStride) {
    constexpr int STAGE_BYTES = 2 * 128 * 128;
    constexpr int STAGES = 3;

    extern __shared__ __align__(128) char smem[];
    const uint32_t smem_b = smem_u32(smem);

    const int tid  = threadIdx.x;
    const int wid  = tid >> 5;
    const int lane = tid & 31;
    const int g    = lane >> 2;
    const int t    = lane & 3;
    const int rl   = lane & 7;
    const int l3   = (lane >> 3) & 1;
    const int l4   = lane >> 4;

    const int warpRow = wid & 1;
    const int warpCol = wid >> 1;
    const int rowBase = blockIdx.y * 128;
    const int colBase = blockIdx.x * 128;
    const int kbase   = blockIdx.z * Kloc;

    float acc[4][4][4];
#pragma unroll
    for (int i = 0; i < 4; i++)
#pragma unroll
        for (int j = 0; j < 4; j++)
#pragma unroll
            for (int q = 0; q < 4; q++) acc[i][j][q] = 0.f;

    const int nchunk = Kloc / 64;

    auto load_stage = [&](int kc, int s) {
        if (kc < nchunk) {
            const uint32_t base = smem_b + (uint32_t)s * STAGE_BYTES;
            const int rw = wid * 4 + (lane >> 3);
            const int un = lane & 7;
#pragma unroll
            for (int it = 0; it < 4; it++) {
                const int r = it * 32 + rw;
                const uint32_t sw = (uint32_t)((un ^ (r & 7)) << 4);
                cp16(base + (uint32_t)r * 128 + sw,
                     A + (size_t)(rowBase + r) * lda + kbase + kc * 64 + un * 8);
                cp16(base + 16384u + (uint32_t)r * 128 + sw,
                     Bt + (size_t)(colBase + r) * ldb + kbase + kc * 64 + un * 8);
            }
        }
        CP_COMMIT();
    };

    uint32_t rowOffA[4], colOffB[2];
#pragma unroll
    for (int mt = 0; mt < 4; mt++)
        rowOffA[mt] = (uint32_t)(warpRow * 64 + mt * 16 + l3 * 8 + rl) * 128;
#pragma unroll
    for (int n2 = 0; n2 < 2; n2++)
        colOffB[n2] = 16384u + (uint32_t)(warpCol * 32 + n2 * 16 + l4 * 8 + rl) * 128;

    load_stage(0, 0);
    load_stage(1, 1);

    int sidx = 0;
    for (int i = 0; i < nchunk; i++) {
        CP_WAIT1();
        __syncthreads();
        int snext = sidx + 2; if (snext >= STAGES) snext -= STAGES;
        load_stage(i + 2, snext);

        const uint32_t st = smem_b + (uint32_t)sidx * STAGE_BYTES;

#pragma unroll
        for (int ks = 0; ks < 4; ks++) {
            const uint32_t offA = (uint32_t)(((ks * 2 + l4) ^ rl) << 4);
            const uint32_t offB = (uint32_t)(((ks * 2 + l3) ^ rl) << 4);
            uint32_t afr[4][4], bfr[4][2];
#pragma unroll
            for (int mt = 0; mt < 4; mt++)
                LDSM4(afr[mt][0], afr[mt][1], afr[mt][2], afr[mt][3],
                      st + rowOffA[mt] + offA);
#pragma unroll
            for (int n2 = 0; n2 < 2; n2++)
                LDSM4(bfr[2 * n2][0], bfr[2 * n2][1], bfr[2 * n2 + 1][0], bfr[2 * n2 + 1][1],
                      st + colOffB[n2] + offB);
#pragma unroll
            for (int mt = 0; mt < 4; mt++)
#pragma unroll
                for (int nt = 0; nt < 4; nt++)
                    mma_bf16(acc[mt][nt], afr[mt], bfr[nt]);
        }
        sidx++; if (sidx >= STAGES) sidx -= STAGES;
    }

    const int rW = rowBase + warpRow * 64;
    const int cW = colBase + warpCol * 32;
#pragma unroll
    for (int mt = 0; mt < 4; mt++) {
#pragma unroll
        for (int nt = 0; nt < 4; nt++) {
            const int r0 = rW + mt * 16 + g;
            const int r1 = r0 + 8;
            const int c0 = cW + nt * 8 + 2 * t;
            float v0 = acc[mt][nt][0], v1 = acc[mt][nt][1];
            float v2 = acc[mt][nt][2], v3 = acc[mt][nt][3];
            if (EPI == 1) {
                const float b0 = E[c0], b1 = E[c0 + 1];
                v0 = softplus_f(v0 + b0);
                v1 = softplus_f(v1 + b1);
                v2 = softplus_f(v2 + b0);
                v3 = softplus_f(v3 + b1);
            } else if (EPI == 2) {
                const float2 e0 = *(const float2*)(E + (size_t)r0 * ldc + c0);
                const float2 e1 = *(const float2*)(E + (size_t)r1 * ldc + c0);
                v0 += e0.x; v1 += e0.y; v2 += e1.x; v3 += e1.y;
            }
            if (OBF) {
                __nv_bfloat16* C = (__nv_bfloat16*)Cv + (size_t)blockIdx.z * partStride;
                *(__nv_bfloat162*)(C + (size_t)r0 * ldc + c0) = __floats2bfloat162_rn(v0, v1);
                *(__nv_bfloat162*)(C + (size_t)r1 * ldc + c0) = __floats2bfloat162_rn(v2, v3);
            } else {
                float* C = (float*)Cv + (size_t)blockIdx.z * partStride;
                *(float2*)(C + (size_t)r0 * ldc + c0) = make_float2(v0, v1);
                *(float2*)(C + (size_t)r1 * ldc + c0) = make_float2(v2, v3);
            }
        }
    }
}

// ---------------- split-K reduce (float4) + dt->bf16 ----------------
__global__ void reduce_xdbl_kernel(const float* __restrict__ part,
                                   float* __restrict__ xdbl,
                                   __nv_bfloat16* __restrict__ dtbf) {
    const int i4 = blockIdx.x * blockDim.x + threadIdx.x;    // BL*GP/4
    const size_t S4 = (size_t)BL * GP / 4;
    const float4* p4 = (const float4*)part;
    const float4 a = p4[i4], b = p4[i4 + S4], c = p4[i4 + 2 * S4], d = p4[i4 + 3 * S4];
    float4 s;
    s.x = a.x + b.x + c.x + d.x;
    s.y = a.y + b.y + c.y + d.y;
    s.z = a.z + b.z + c.z + d.z;
    s.w = a.w + b.w + c.w + d.w;
    ((float4*)xdbl)[i4] = s;
    const int col = (i4 << 2) & (GP - 1);
    if (col < RANK) {
        const int row = i4 >> 5;
        __nv_bfloat16* dp = dtbf + (size_t)row * RANK + col;
        *(__nv_bfloat162*)(dp)     = __floats2bfloat162_rn(s.x, s.y);
        *(__nv_bfloat162*)(dp + 2) = __floats2bfloat162_rn(s.z, s.w);
    }
}

// ---------------- scan pass A : 2 channels per thread ----------------
__global__ void scanA_kernel(const __nv_bfloat16* __restrict__ delta,
                             const __nv_bfloat16* __restrict__ u,
                             const float* __restrict__ xdbl,
                             const float* __restrict__ A_log,
                             float* __restrict__ S, float* __restrict__ dsum) {
    __shared__ float Bs[CHL * DS];
    const int tid = threadIdx.x;                 // 128 threads, 256 channels
    const int d0 = blockIdx.x * 256 + tid * 2;
    const int c = blockIdx.y, b = blockIdx.z;
    const int l0 = c * CHL;

    const float4* xd4 = (const float4*)xdbl;
    for (int i = tid; i < CHL * 4; i += 128) {
        const int l = i >> 2, q = i & 3;
        ((float4*)Bs)[i] = xd4[((size_t)(b * LSEQ + l0 + l)) * 32 + 16 + q];
    }

    float Av0[DS], Av1[DS];
#pragma unroll
    for (int n = 0; n < DS; n++) {
        Av0[n] = -__expf(A_log[d0 * DS + n]);
        Av1[n] = -__expf(A_log[(d0 + 1) * DS + n]);
    }
    bool st = (Av0[0] < 0.f) && (Av1[0] < 0.f);
#pragma unroll
    for (int n = 1; n < DS; n++) {
        st = st && (fabsf(Av0[n] - (n + 1) * Av0[0]) <= 1e-5f * fabsf(Av0[n]));
        st = st && (fabsf(Av1[n] - (n + 1) * Av1[0]) <= 1e-5f * fabsf(Av1[n]));
    }
    __syncthreads();

    float h0[DS], h1[DS];
#pragma unroll
    for (int n = 0; n < DS; n++) { h0[n] = 0.f; h1[n] = 0.f; }
    float ds0 = 0.f, ds1 = 0.f;

    size_t p = ((size_t)(b * LSEQ + l0)) * DI + d0;
    if (st) {
        const float a0 = Av0[0], a1 = Av1[0];
        for (int l = 0; l < CHL; l++, p += DI) {
            const float2 dv = __bfloat1622float2(*(const __nv_bfloat162*)(delta + p));
            const float2 uv = __bfloat1622float2(*(const __nv_bfloat162*)(u + p));
            ds0 += dv.x; ds1 += dv.y;
            const float cv0 = dv.x * uv.x, cv1 = dv.y * uv.y;
            float pw[DS];
            powers16(__expf(dv.x * a0), pw);
#pragma unroll
            for (int n = 0; n < DS; n++)
                h0[n] = fmaf(pw[n], h0[n], cv0 * Bs[l * DS + n]);
            powers16(__expf(dv.y * a1), pw);
#pragma unroll
            for (int n = 0; n < DS; n++)
                h1[n] = fmaf(pw[n], h1[n], cv1 * Bs[l * DS + n]);
        }
    } else {
        for (int l = 0; l < CHL; l++, p += DI) {
            const float2 dv = __bfloat1622float2(*(const __nv_bfloat162*)(delta + p));
            const float2 uv = __bfloat1622float2(*(const __nv_bfloat162*)(u + p));
            ds0 += dv.x; ds1 += dv.y;
            const float cv0 = dv.x * uv.x, cv1 = dv.y * uv.y;
#pragma unroll
            for (int n = 0; n < DS; n++) {
                h0[n] = fmaf(__expf(dv.x * Av0[n]), h0[n], cv0 * Bs[l * DS + n]);
                h1[n] = fmaf(__expf(dv.y * Av1[n]), h1[n], cv1 * Bs[l * DS + n]);
            }
        }
    }

    const size_t o = ((size_t)((b * NCH + c) * DI) + d0) * DS;
#pragma unroll
    for (int n = 0; n < DS; n++) { S[o + n] = h0[n]; S[o + DS + n] = h1[n]; }
    const size_t od = (size_t)(b * NCH + c) * DI + d0;
    dsum[od] = ds0; dsum[od + 1] = ds1;
}

// ---------------- scan pass B ----------------
__global__ void scanB_kernel(const float* __restrict__ S,
                             const float* __restrict__ dsum,
                             const float* __restrict__ A_log,
                             float* __restrict__ H0) {
    const int idx = blockIdx.x * blockDim.x + threadIdx.x;
    const int n = idx & 15;
    const int d = (idx >> 4) & (DI - 1);
    const int b = idx >> 15;
    const float Av = -__expf(A_log[d * DS + n]);
    float h = 0.f;
#pragma unroll
    for (int c = 0; c < NCH; c++) {
        const size_t o = ((size_t)((b * NCH + c) * DI) + d) * DS + n;
        H0[o] = h;
        const float P = __expf(dsum[(size_t)(b * NCH + c) * DI + d] * Av);
        h = fmaf(P, h, S[o]);
    }
}

// ---------------- scan pass C : 2 channels per thread ----------------
__global__ void scanC_kernel(const __nv_bfloat16* __restrict__ delta,
                             const __nv_bfloat16* __restrict__ u,
                             const float* __restrict__ xdbl,
                             const __nv_bfloat16* __restrict__ xz,
                             const float* __restrict__ A_log,
                             const float* __restrict__ Dskip,
                             const float* __restrict__ H0,
                             __nv_bfloat16* __restrict__ yg) {
    __shared__ float Bs[CHL * DS];
    __shared__ float Cs[CHL * DS];
    const int tid = threadIdx.x;
    const int d0 = blockIdx.x * 256 + tid * 2;
    const int c = blockIdx.y, b = blockIdx.z;
    const int l0 = c * CHL;

    const float4* xd4 = (const float4*)xdbl;
    for (int i = tid; i < CHL * 4; i += 128) {
        const int l = i >> 2, q = i & 3;
        const size_t row = ((size_t)(b * LSEQ + l0 + l)) * 32;
        ((float4*)Bs)[i] = xd4[row + 16 + q];
        ((float4*)Cs)[i] = xd4[row + 20 + q];
    }

    float Av0[DS], Av1[DS];
#pragma unroll
    for (int n = 0; n < DS; n++) {
        Av0[n] = -__expf(A_log[d0 * DS + n]);
        Av1[n] = -__expf(A_log[(d0 + 1) * DS + n]);
    }
    bool st = (Av0[0] < 0.f) && (Av1[0] < 0.f);
#pragma unroll
    for (int n = 1; n < DS; n++) {
        st = st && (fabsf(Av0[n] - (n + 1) * Av0[0]) <= 1e-5f * fabsf(Av0[n]));
        st = st && (fabsf(Av1[n] - (n + 1) * Av1[0]) <= 1e-5f * fabsf(Av1[n]));
    }
    const float dsk0 = Dskip[d0], dsk1 = Dskip[d0 + 1];
    __syncthreads();

    float h0[DS], h1[DS];
    const size_t ho = ((size_t)((b * NCH + c) * DI) + d0) * DS;
#pragma unroll
    for (int n = 0; n < DS; n++) { h0[n] = H0[ho + n]; h1[n] = H0[ho + DS + n]; }

    size_t p = ((size_t)(b * LSEQ + l0)) * DI + d0;
    const float a0 = Av0[0], a1 = Av1[0];
    for (int l = 0; l < CHL; l++, p += DI) {
        const float2 dv = __bfloat1622float2(*(const __nv_bfloat162*)(delta + p));
        const float2 uv = __bfloat1622float2(*(const __nv_bfloat162*)(u + p));
        const float2 zv = __bfloat1622float2(*(const __nv_bfloat162*)(
            xz + ((size_t)(b * LSEQ + l0 + l)) * (2 * DI) + DI + d0));
        const float cv0 = dv.x * uv.x, cv1 = dv.y * uv.y;
        float pw[DS];
        float ya = 0.f, yb = 0.f;
        if (st) powers16(__expf(dv.x * a0), pw);
        else {
#pragma unroll
            for (int n = 0; n < DS; n++) pw[n] = __expf(dv.x * Av0[n]);
        }
#pragma unroll
        for (int n = 0; n < DS; n++) {
            h0[n] = fmaf(pw[n], h0[n], cv0 * Bs[l * DS + n]);
            ya = fmaf(h0[n], Cs[l * DS + n], ya);
        }
        if (st) powers16(__expf(dv.y * a1), pw);
        else {
#pragma unroll
            for (int n = 0; n < DS; n++) pw[n] = __expf(dv.y * Av1[n]);
        }
#pragma unroll
        for (int n = 0; n < DS; n++) {
            h1[n] = fmaf(pw[n], h1[n], cv1 * Bs[l * DS + n]);
            yb = fmaf(h1[n], Cs[l * DS + n], yb);
        }
        const float y0 = ya + uv.x * dsk0;
        const float y1 = yb + uv.y * dsk1;
        const float s0 = 1.f / (1.f + __expf(-zv.x));
        const float s1 = 1.f / (1.f + __expf(-zv.y));
        *(__nv_bfloat162*)(yg + p) =
            __floats2bfloat162_rn(y0 * (zv.x * s0), y1 * (zv.y * s1));
    }
}

// ---------------- launch ----------------
extern "C" void kernel_launch(void* const* d_in, const int* in_sizes, int n_in,
                              void* d_out, int out_size) {
    const float* x       = (const float*)d_in[0];
    const float* ln_g    = (const float*)d_in[1];
    const float* ln_b    = (const float*)d_in[2];
    const float* W_in    = (const float*)d_in[3];
    const float* conv_w  = (const float*)d_in[4];
    const float* conv_b  = (const float*)d_in[5];
    const float* W_xproj = (const float*)d_in[6];
    const float* W_dt    = (const float*)d_in[7];
    const float* b_dt    = (const float*)d_in[8];
    const float* A_log   = (const float*)d_in[9];
    const float* D_skip  = (const float*)d_in[10];
    const float* W_out   = (const float*)d_in[11];
    float* out = (float*)d_out;

    __nv_bfloat16 *xn, *xzbf, *ubf, *dtbf, *delbf, *yg, *wtin, *wtout, *wtxp, *wtdt;
    float *part, *xdbl, *Sb, *H0b, *dsumb;
    cudaGetSymbolAddress((void**)&xn,    g_xn_bf);
    cudaGetSymbolAddress((void**)&xzbf,  g_xz_bf);
    cudaGetSymbolAddress((void**)&ubf,   g_u_bf);
    cudaGetSymbolAddress((void**)&part,  g_part);
    cudaGetSymbolAddress((void**)&xdbl,  g_xdbl);
    cudaGetSymbolAddress((void**)&dtbf,  g_dt_bf);
    cudaGetSymbolAddress((void**)&delbf, g_del_bf);
    cudaGetSymbolAddress((void**)&yg,    g_yg_bf);
    cudaGetSymbolAddress((void**)&Sb,    g_S);
    cudaGetSymbolAddress((void**)&H0b,   g_H0);
    cudaGetSymbolAddress((void**)&dsumb, g_dsum);
    cudaGetSymbolAddress((void**)&wtin,  g_wt_in);
    cudaGetSymbolAddress((void**)&wtout, g_wt_out);
    cudaGetSymbolAddress((void**)&wtxp,  g_wt_xp);
    cudaGetSymbolAddress((void**)&wtdt,  g_wt_dt);

    const int smemBytes = 3 * 2 * 128 * 128;   // 98304
    cudaFuncSetAttribute(mma_gemm_kernel<0, true>,  cudaFuncAttributeMaxDynamicSharedMemorySize, smemBytes);
    cudaFuncSetAttribute(mma_gemm_kernel<0, false>, cudaFuncAttributeMaxDynamicSharedMemorySize, smemBytes);
    cudaFuncSetAttribute(mma_gemm_kernel<1, true>,  cudaFuncAttributeMaxDynamicSharedMemorySize, smemBytes);
    cudaFuncSetAttribute(mma_gemm_kernel<2, false>, cudaFuncAttributeMaxDynamicSharedMemorySize, smemBytes);

    // 1) prep
    prep_kernel<<<3264 + BL, dim3(32, 8)>>>(x, ln_g, ln_b, W_in, W_out, W_xproj, W_dt,
                                            xn, wtin, wtout, wtxp, wtdt);
    // 2) xz = xn @ W_in -> bf16
    mma_gemm_kernel<0, true><<<dim3((2 * DI) / 128, BL / 128, 1), 256, smemBytes>>>(
        xn, wtin, xzbf, BL, 2 * DI, DM, DM, 2 * DI, nullptr, DM, 0);
    // 3) conv + silu
    conv_silu_kernel<<<((size_t)BL * DI / 8) / 256, 256>>>(xzbf, conv_w, conv_b, ubf);
    // 4) x_dbl partials (split-K)  (PROFILED)
    mma_gemm_kernel<0, false><<<dim3(GP / 128, BL / 128, SPLITK), 256, smemBytes>>>(
        ubf, wtxp, part, BL, GP, DI, DI, GP, nullptr, DI / SPLITK, (size_t)BL * GP);
    // 5) reduce
    reduce_xdbl_kernel<<<(BL * GP / 4) / 256, 256>>>(part, xdbl, dtbf);
    // 6) delta = softplus(dt @ W_dt + b_dt) -> bf16
    mma_gemm_kernel<1, true><<<dim3(DI / 128, BL / 128, 1), 256, smemBytes>>>(
        dtbf, wtdt, delbf, BL, DI, RANK, RANK, DI, b_dt, RANK, 0);
    // 7-9) chunked selective scan (2 channels/thread, NCH=32)
    scanA_kernel<<<dim3(DI / 256, NCH, BATCH), 128>>>(delbf, ubf, xdbl, A_log, Sb, dsumb);
    scanB_kernel<<<(BATCH * DI * DS) / 256, 256>>>(Sb, dsumb, A_log, H0b);
    scanC_kernel<<<dim3(DI / 256, NCH, BATCH), 128>>>(delbf, ubf, xdbl, xzbf,
                                                      A_log, D_skip, H0b, yg);
    // 10) out = x + yg @ W_out
    mma_gemm_kernel<2, false><<<dim3(DM / 128, BL / 128, 1), 256, smemBytes>>>(
        yg, wtout, out, BL, DM, DI, DI, DM, x, DI, 0);
}

// round 11
// speedup vs baseline: 1.4073x; 1.3907x over previous
#include <cuda_runtime.h>
#include <cuda_bf16.h>
#include <math.h>
#include <stdint.h>

// ---------------- problem constants ----------------
#define BATCH   2
#define LSEQ    2048
#define DM      1024
#define DI      2048
#define DS      16
#define DC      4
#define RANK    64
#define GDIM    96
#define GP      128
#define BL      (BATCH*LSEQ)  // 4096
#define SPLITK  4
#define NCH     16
#define CHL     (LSEQ/NCH)    // 128

// ---------------- scratch ----------------
__device__ __nv_bfloat16 g_xn_bf  [(size_t)BL*DM];
__device__ __nv_bfloat16 g_xz_bf  [(size_t)BL*2*DI];
__device__ __nv_bfloat16 g_u_bf   [(size_t)BL*DI];
__device__ float         g_part   [(size_t)SPLITK*BL*GP];
__device__ float         g_xdbl   [(size_t)BL*GP];
__device__ __nv_bfloat16 g_dt_bf  [(size_t)BL*RANK];
__device__ __nv_bfloat16 g_del_bf [(size_t)BL*DI];
__device__ __nv_bfloat16 g_yg_bf  [(size_t)BL*DI];
__device__ float         g_S      [(size_t)BATCH*NCH*DI*DS];
__device__ float         g_H0     [(size_t)BATCH*NCH*DI*DS];
__device__ float         g_dsum   [(size_t)BATCH*NCH*DI];
__device__ __nv_bfloat16 g_wt_in  [(size_t)(2*DI)*DM];
__device__ __nv_bfloat16 g_wt_out [(size_t)DM*DI];
__device__ __nv_bfloat16 g_wt_xp  [(size_t)GP*DI];
__device__ __nv_bfloat16 g_wt_dt  [(size_t)DI*RANK];

// ---------------- helpers ----------------
__device__ __forceinline__ uint32_t smem_u32(const void* p) {
    uint32_t a;
    asm("{ .reg .u64 t; cvta.to.shared.u64 t, %1; cvt.u32.u64 %0, t; }" : "=r"(a) : "l"(p));
    return a;
}
__device__ __forceinline__ void cp16(uint32_t dst, const void* src) {
    asm volatile("cp.async.cg.shared.global [%0], [%1], 16;" :: "r"(dst), "l"(src));
}
#define CP_COMMIT() asm volatile("cp.async.commit_group;")
#define CP_WAIT1()  asm volatile("cp.async.wait_group 1;")

__device__ __forceinline__ void mma_bf16(float* c, const uint32_t* a, const uint32_t* b) {
    asm volatile(
        "mma.sync.aligned.m16n8k16.row.col.f32.bf16.bf16.f32 "
        "{%0,%1,%2,%3}, {%4,%5,%6,%7}, {%8,%9}, {%0,%1,%2,%3};"
        : "+f"(c[0]), "+f"(c[1]), "+f"(c[2]), "+f"(c[3])
        : "r"(a[0]), "r"(a[1]), "r"(a[2]), "r"(a[3]), "r"(b[0]), "r"(b[1]));
}
#define LDSM4(r0, r1, r2, r3, addr) \
    asm volatile("ldmatrix.sync.aligned.m8n8.x4.shared.b16 {%0,%1,%2,%3}, [%4];" \
        : "=r"(r0), "=r"(r1), "=r"(r2), "=r"(r3) : "r"(addr))

__device__ __forceinline__ float softplus_f(float t) {
    return (t > 20.f) ? t : __logf(1.f + __expf(t));
}
__device__ __forceinline__ void powers16(float w, float* pw) {
    const float w2 = w * w, w4 = w2 * w2, w8 = w4 * w4;
    pw[0]  = w;        pw[1]  = w2;       pw[2]  = w2 * w;   pw[3]  = w4;
    pw[4]  = w4 * w;   pw[5]  = w4 * w2;  pw[6]  = w4 * pw[2]; pw[7] = w8;
    pw[8]  = w8 * w;   pw[9]  = w8 * w2;  pw[10] = w8 * pw[2]; pw[11] = w8 * w4;
    pw[12] = w8 * pw[4]; pw[13] = w8 * pw[5]; pw[14] = w8 * pw[6]; pw[15] = w8 * w8;
}

// ---------------- prep: all weight transposes + layernorm, one launch -------
__device__ __forceinline__ void transpose64(const float* in, __nv_bfloat16* out,
                                            int K, int Nsrc, int Nout,
                                            int kb, int nb, int tx, int ty,
                                            float (*t)[33]) {
#pragma unroll
    for (int r = ty; r < 64; r += 8) {
        const int n = nb + tx;
        t[r][tx] = (n < Nsrc) ? in[(size_t)(kb + r) * Nsrc + n] : 0.f;
    }
    __syncthreads();
#pragma unroll
    for (int j = ty; j < 32; j += 8) {
        const int n = nb + j;
        if (n < Nout) {
            const __nv_bfloat162 v = __floats2bfloat162_rn(t[tx * 2][j], t[tx * 2 + 1][j]);
            *(__nv_bfloat162*)(out + (size_t)n * K + kb + tx * 2) = v;
        }
    }
}

__global__ void prep_kernel(const float* __restrict__ x,
                            const float* __restrict__ gamma,
                            const float* __restrict__ beta,
                            const float* __restrict__ Win,
                            const float* __restrict__ Wout,
                            const float* __restrict__ Wxp,
                            const float* __restrict__ Wdt,
                            __nv_bfloat16* __restrict__ xn,
                            __nv_bfloat16* __restrict__ wtin,
                            __nv_bfloat16* __restrict__ wtout,
                            __nv_bfloat16* __restrict__ wtxp,
                            __nv_bfloat16* __restrict__ wtdt) {
    __shared__ float t[64][33];
    const int tx = threadIdx.x, ty = threadIdx.y;
    int b = blockIdx.x;
    if (b < 2048) {
        transpose64(Win, wtin, DM, 2 * DI, 2 * DI, (b & 15) * 64, (b >> 4) * 32, tx, ty, t);
    } else if (b < 3072) {
        b -= 2048;
        transpose64(Wout, wtout, DI, DM, DM, (b & 31) * 64, (b >> 5) * 32, tx, ty, t);
    } else if (b < 3200) {
        b -= 3072;
        transpose64(Wxp, wtxp, DI, GDIM, GP, (b & 31) * 64, (b >> 5) * 32, tx, ty, t);
    } else if (b < 3264) {
        b -= 3200;
        transpose64(Wdt, wtdt, RANK, DI, DI, 0, b * 32, tx, ty, t);
    } else {
        const int row = b - 3264;
        const int tid = ty * 32 + tx;
        const float4 v = ((const float4*)(x + (size_t)row * DM))[tid];
        float s  = v.x + v.y + v.z + v.w;
        float s2 = v.x * v.x + v.y * v.y + v.z * v.z + v.w * v.w;
#pragma unroll
        for (int o = 16; o > 0; o >>= 1) {
            s  += __shfl_xor_sync(0xffffffffu, s,  o);
            s2 += __shfl_xor_sync(0xffffffffu, s2, o);
        }
        if ((tid & 31) == 0) { t[0][tid >> 5] = s; t[1][tid >> 5] = s2; }
        __syncthreads();
        s = 0.f; s2 = 0.f;
#pragma unroll
        for (int i = 0; i < 8; i++) { s += t[0][i]; s2 += t[1][i]; }
        const float mean = s * (1.f / DM);
        const float var  = s2 * (1.f / DM) - mean * mean;
        const float rstd = rsqrtf(var + 1e-5f);
        const float4 gm = ((const float4*)gamma)[tid];
        const float4 bt = ((const float4*)beta)[tid];
        __nv_bfloat16* orow = xn + (size_t)row * DM + tid * 4;
        *(__nv_bfloat162*)(orow) =
            __floats2bfloat162_rn((v.x - mean) * rstd * gm.x + bt.x,
                                  (v.y - mean) * rstd * gm.y + bt.y);
        *(__nv_bfloat162*)(orow + 2) =
            __floats2bfloat162_rn((v.z - mean) * rstd * gm.z + bt.z,
                                  (v.w - mean) * rstd * gm.w + bt.w);
    }
}

// ---------------- conv + silu: 8 channels x 4 timesteps, sliding window -----
__global__ void conv_silu_kernel(const __nv_bfloat16* __restrict__ xz,
                                 const float* __restrict__ w,
                                 const float* __restrict__ bias,
                                 __nv_bfloat16* __restrict__ ubf) {
    const int idx = blockIdx.x * blockDim.x + threadIdx.x;  // (BL/4)*(DI/8)
    const int dg  = idx & 255;
    const int bq  = idx >> 8;
    const int bl0 = bq * 4;
    const int l0  = bl0 & (LSEQ - 1);    // multiple of 4; batch edge only at l0==0
    const int d0  = dg << 3;

    float bv[8];
    {
        const float4 b0 = *(const float4*)(bias + d0);
        const float4 b1 = *(const float4*)(bias + d0 + 4);
        bv[0] = b0.x; bv[1] = b0.y; bv[2] = b0.z; bv[3] = b0.w;
        bv[4] = b1.x; bv[5] = b1.y; bv[6] = b1.z; bv[7] = b1.w;
    }
    float wv[4][8];
#pragma unroll
    for (int k = 0; k < 8; k++) {
        const float4 wk = *(const float4*)(w + (d0 + k) * 4);
        wv[0][k] = wk.x; wv[1][k] = wk.y; wv[2][k] = wk.z; wv[3][k] = wk.w;
    }

    auto load_row = [&](int bl, bool valid, float* r) {
        if (valid) {
            const uint4 q = *(const uint4*)(xz + (size_t)bl * (2 * DI) + d0);
            const __nv_bfloat162* h = (const __nv_bfloat162*)&q;
#pragma unroll
            for (int k2 = 0; k2 < 4; k2++) {
                const float2 f = __bfloat1622float2(h[k2]);
                r[k2 * 2] = f.x; r[k2 * 2 + 1] = f.y;
            }
        } else {
#pragma unroll
            for (int k = 0; k < 8; k++) r[k] = 0.f;
        }
    };

    float w0[8], w1[8], w2[8], w3[8];
    const bool interior = (l0 != 0);
    load_row(bl0 - 3, interior, w0);
    load_row(bl0 - 2, interior, w1);
    load_row(bl0 - 1, interior, w2);

#pragma unroll
    for (int t = 0; t < 4; t++) {
        load_row(bl0 + t, true, w3);
        uint4 oq;
        __nv_bfloat162* oh = (__nv_bfloat162*)&oq;
#pragma unroll
        for (int k2 = 0; k2 < 4; k2++) {
            float a0 = bv[k2 * 2], a1 = bv[k2 * 2 + 1];
            a0 = fmaf(wv[0][k2 * 2], w0[k2 * 2], a0);
            a1 = fmaf(wv[0][k2 * 2 + 1], w0[k2 * 2 + 1], a1);
            a0 = fmaf(wv[1][k2 * 2], w1[k2 * 2], a0);
            a1 = fmaf(wv[1][k2 * 2 + 1], w1[k2 * 2 + 1], a1);
            a0 = fmaf(wv[2][k2 * 2], w2[k2 * 2], a0);
            a1 = fmaf(wv[2][k2 * 2 + 1], w2[k2 * 2 + 1], a1);
            a0 = fmaf(wv[3][k2 * 2], w3[k2 * 2], a0);
            a1 = fmaf(wv[3][k2 * 2 + 1], w3[k2 * 2 + 1], a1);
            const float s0 = a0 / (1.f + __expf(-a0));
            const float s1 = a1 / (1.f + __expf(-a1));
            oh[k2] = __floats2bfloat162_rn(s0, s1);
        }
        *(uint4*)(ubf + (size_t)(bl0 + t) * DI + d0) = oq;
#pragma unroll
        for (int k = 0; k < 8; k++) { w0[k] = w1[k]; w1[k] = w2[k]; w2[k] = w3[k]; }
    }
}

// ---------------- bf16 mma.sync GEMM with ldmatrix (R8 proven) ----------------
// C[M,N] = A[M,K] @ Bt[N,K]^T ; EPI: 0 none | 1 softplus(acc+E[col]) | 2 acc+E
template <int EPI, bool OBF>
__global__ __launch_bounds__(256, 2)
void mma_gemm_kernel(const __nv_bfloat16* __restrict__ A,
                     const __nv_bfloat16* __restrict__ Bt,
                     void* __restrict__ Cv, int M, int N,
                     int lda, int ldb, int ldc, const float* __restrict__ E,
                     int Kloc, size_t partStride) {
    constexpr int STAGE_BYTES = 2 * 128 * 128;
    constexpr int STAGES = 3;

    extern __shared__ __align__(128) char smem[];
    const uint32_t smem_b = smem_u32(smem);

    const int tid  = threadIdx.x;
    const int wid  = tid >> 5;
    const int lane = tid & 31;
    const int g    = lane >> 2;
    const int t    = lane & 3;
    const int rl   = lane & 7;
    const int l3   = (lane >> 3) & 1;
    const int l4   = lane >> 4;

    const int warpRow = wid & 1;
    const int warpCol = wid >> 1;
    const int rowBase = blockIdx.y * 128;
    const int colBase = blockIdx.x * 128;
    const int kbase   = blockIdx.z * Kloc;

    float acc[4][4][4];
#pragma unroll
    for (int i = 0; i < 4; i++)
#pragma unroll
        for (int j = 0; j < 4; j++)
#pragma unroll
            for (int q = 0; q < 4; q++) acc[i][j][q] = 0.f;

    const int nchunk = Kloc / 64;

    auto load_stage = [&](int kc, int s) {
        if (kc < nchunk) {
            const uint32_t base = smem_b + (uint32_t)s * STAGE_BYTES;
            const int rw = wid * 4 + (lane >> 3);
            const int un = lane & 7;
#pragma unroll
            for (int it = 0; it < 4; it++) {
                const int r = it * 32 + rw;
                const uint32_t sw = (uint32_t)((un ^ (r & 7)) << 4);
                cp16(base + (uint32_t)r * 128 + sw,
                     A + (size_t)(rowBase + r) * lda + kbase + kc * 64 + un * 8);
                cp16(base + 16384u + (uint32_t)r * 128 + sw,
                     Bt + (size_t)(colBase + r) * ldb + kbase + kc * 64 + un * 8);
            }
        }
        CP_COMMIT();
    };

    uint32_t rowOffA[4], colOffB[2];
#pragma unroll
    for (int mt = 0; mt < 4; mt++)
        rowOffA[mt] = (uint32_t)(warpRow * 64 + mt * 16 + l3 * 8 + rl) * 128;
#pragma unroll
    for (int n2 = 0; n2 < 2; n2++)
        colOffB[n2] = 16384u + (uint32_t)(warpCol * 32 + n2 * 16 + l4 * 8 + rl) * 128;

    load_stage(0, 0);
    load_stage(1, 1);

    int sidx = 0;
    for (int i = 0; i < nchunk; i++) {
        CP_WAIT1();
        __syncthreads();
        int snext = sidx + 2; if (snext >= STAGES) snext -= STAGES;
        load_stage(i + 2, snext);

        const uint32_t st = smem_b + (uint32_t)sidx * STAGE_BYTES;

#pragma unroll
        for (int ks = 0; ks < 4; ks++) {
            const uint32_t offA = (uint32_t)(((ks * 2 + l4) ^ rl) << 4);
            const uint32_t offB = (uint32_t)(((ks * 2 + l3) ^ rl) << 4);
            uint32_t afr[4][4], bfr[4][2];
#pragma unroll
            for (int mt = 0; mt < 4; mt++)
                LDSM4(afr[mt][0], afr[mt][1], afr[mt][2], afr[mt][3],
                      st + rowOffA[mt] + offA);
#pragma unroll
            for (int n2 = 0; n2 < 2; n2++)
                LDSM4(bfr[2 * n2][0], bfr[2 * n2][1], bfr[2 * n2 + 1][0], bfr[2 * n2 + 1][1],
                      st + colOffB[n2] + offB);
#pragma unroll
            for (int mt = 0; mt < 4; mt++)
#pragma unroll
                for (int nt = 0; nt < 4; nt++)
                    mma_bf16(acc[mt][nt], afr[mt], bfr[nt]);
        }
        sidx++; if (sidx >= STAGES) sidx -= STAGES;
    }

    const int rW = rowBase + warpRow * 64;
    const int cW = colBase + warpCol * 32;
#pragma unroll
    for (int mt = 0; mt < 4; mt++) {
#pragma unroll
        for (int nt = 0; nt < 4; nt++) {
            const int r0 = rW + mt * 16 + g;
            const int r1 = r0 + 8;
            const int c0 = cW + nt * 8 + 2 * t;
            float v0 = acc[mt][nt][0], v1 = acc[mt][nt][1];
            float v2 = acc[mt][nt][2], v3 = acc[mt][nt][3];
            if (EPI == 1) {
                const float b0 = E[c0], b1 = E[c0 + 1];
                v0 = softplus_f(v0 + b0);
                v1 = softplus_f(v1 + b1);
                v2 = softplus_f(v2 + b0);
                v3 = softplus_f(v3 + b1);
            } else if (EPI == 2) {
                const float2 e0 = *(const float2*)(E + (size_t)r0 * ldc + c0);
                const float2 e1 = *(const float2*)(E + (size_t)r1 * ldc + c0);
                v0 += e0.x; v1 += e0.y; v2 += e1.x; v3 += e1.y;
            }
            if (OBF) {
                __nv_bfloat16* C = (__nv_bfloat16*)Cv + (size_t)blockIdx.z * partStride;
                *(__nv_bfloat162*)(C + (size_t)r0 * ldc + c0) = __floats2bfloat162_rn(v0, v1);
                *(__nv_bfloat162*)(C + (size_t)r1 * ldc + c0) = __floats2bfloat162_rn(v2, v3);
            } else {
                float* C = (float*)Cv + (size_t)blockIdx.z * partStride;
                *(float2*)(C + (size_t)r0 * ldc + c0) = make_float2(v0, v1);
                *(float2*)(C + (size_t)r1 * ldc + c0) = make_float2(v2, v3);
            }
        }
    }
}

// ---------------- split-K reduce (float4) + dt->bf16 ----------------
__global__ void reduce_xdbl_kernel(const float* __restrict__ part,
                                   float* __restrict__ xdbl,
                                   __nv_bfloat16* __restrict__ dtbf) {
    const int i4 = blockIdx.x * blockDim.x + threadIdx.x;    // BL*GP/4
    const size_t S4 = (size_t)BL * GP / 4;
    const float4* p4 = (const float4*)part;
    const float4 a = p4[i4], b = p4[i4 + S4], c = p4[i4 + 2 * S4], d = p4[i4 + 3 * S4];
    float4 s;
    s.x = a.x + b.x + c.x + d.x;
    s.y = a.y + b.y + c.y + d.y;
    s.z = a.z + b.z + c.z + d.z;
    s.w = a.w + b.w + c.w + d.w;
    ((float4*)xdbl)[i4] = s;
    const int col = (i4 << 2) & (GP - 1);
    if (col < RANK) {
        const int row = i4 >> 5;
        __nv_bfloat16* dp = dtbf + (size_t)row * RANK + col;
        *(__nv_bfloat162*)(dp)     = __floats2bfloat162_rn(s.x, s.y);
        *(__nv_bfloat162*)(dp + 2) = __floats2bfloat162_rn(s.z, s.w);
    }
}

// ---------------- scan pass A (R8 layout + distance-2 prefetch) -------------
__global__ void scanA_kernel(const __nv_bfloat16* __restrict__ delta,
                             const __nv_bfloat16* __restrict__ u,
                             const float* __restrict__ xdbl,
                             const float* __restrict__ A_log,
                             float* __restrict__ S, float* __restrict__ dsum) {
    __shared__ float Bs[CHL * DS];
    const int tid = threadIdx.x;
    const int d = blockIdx.x * 128 + tid;
    const int c = blockIdx.y, b = blockIdx.z;
    const int l0 = c * CHL;

    const float4* xd4 = (const float4*)xdbl;
    for (int i = tid; i < CHL * 4; i += 128) {
        const int l = i >> 2, q = i & 3;
        ((float4*)Bs)[i] = xd4[((size_t)(b * LSEQ + l0 + l)) * 32 + 16 + q];
    }

    float Av[DS];
#pragma unroll
    for (int n = 0; n < DS; n++) Av[n] = -__expf(A_log[d * DS + n]);
    bool structured = (Av[0] < 0.f);
#pragma unroll
    for (int n = 1; n < DS; n++)
        structured = structured && (fabsf(Av[n] - (n + 1) * Av[0]) <= 1e-5f * fabsf(Av[n]));
    __syncthreads();

    float h[DS];
#pragma unroll
    for (int n = 0; n < DS; n++) h[n] = 0.f;
    float ds = 0.f;

    size_t p = ((size_t)(b * LSEQ + l0)) * DI + d;
    __nv_bfloat16 dq0 = delta[p],       uq0 = u[p];
    __nv_bfloat16 dq1 = delta[p + DI],  uq1 = u[p + DI];

    for (int l = 0; l < CHL; l++, p += DI) {
        __nv_bfloat16 dq2 = __float2bfloat16(0.f), uq2 = dq2;
        if (l + 2 < CHL) { dq2 = delta[p + 2 * DI]; uq2 = u[p + 2 * DI]; }
        const float dv = __bfloat162float(dq0);
        const float uv = __bfloat162float(uq0);
        ds += dv;
        const float cv = dv * uv;
        float pw[DS];
        if (structured) {
            powers16(__expf(dv * Av[0]), pw);
        } else {
#pragma unroll
            for (int n = 0; n < DS; n++) pw[n] = __expf(dv * Av[n]);
        }
#pragma unroll
        for (int n = 0; n < DS; n++)
            h[n] = fmaf(pw[n], h[n], cv * Bs[l * DS + n]);
        dq0 = dq1; uq0 = uq1; dq1 = dq2; uq1 = uq2;
    }

    const size_t o = ((size_t)((b * NCH + c) * DI) + d) * DS;
#pragma unroll
    for (int n = 0; n < DS; n++) S[o + n] = h[n];
    dsum[(size_t)(b * NCH + c) * DI + d] = ds;
}

// ---------------- scan pass B ----------------
__global__ void scanB_kernel(const float* __restrict__ S,
                             const float* __restrict__ dsum,
                             const float* __restrict__ A_log,
                             float* __restrict__ H0) {
    const int idx = blockIdx.x * blockDim.x + threadIdx.x;
    const int n = idx & 15;
    const int d = (idx >> 4) & (DI - 1);
    const int b = idx >> 15;
    const float Av = -__expf(A_log[d * DS + n]);
    float h = 0.f;
#pragma unroll
    for (int c = 0; c < NCH; c++) {
        const size_t o = ((size_t)((b * NCH + c) * DI) + d) * DS + n;
        H0[o] = h;
        const float P = __expf(dsum[(size_t)(b * NCH + c) * DI + d] * Av);
        h = fmaf(P, h, S[o]);
    }
}

// ---------------- scan pass C (R8 layout + distance-2 prefetch) -------------
__global__ void scanC_kernel(const __nv_bfloat16* __restrict__ delta,
                             const __nv_bfloat16* __restrict__ u,
                             const float* __restrict__ xdbl,
                             const __nv_bfloat16* __restrict__ xz,
                             const float* __restrict__ A_log,
                             const float* __restrict__ Dskip,
                             const float* __restrict__ H0,
                             __nv_bfloat16* __restrict__ yg) {
    __shared__ float Bs[CHL * DS];
    __shared__ float Cs[CHL * DS];
    const int tid = threadIdx.x;
    const int d = blockIdx.x * 128 + tid;
    const int c = blockIdx.y, b = blockIdx.z;
    const int l0 = c * CHL;

    const float4* xd4 = (const float4*)xdbl;
    for (int i = tid; i < CHL * 4; i += 128) {
        const int l = i >> 2, q = i & 3;
        const size_t row = ((size_t)(b * LSEQ + l0 + l)) * 32;
        ((float4*)Bs)[i] = xd4[row + 16 + q];
        ((float4*)Cs)[i] = xd4[row + 20 + q];
    }

    float Av[DS];
#pragma unroll
    for (int n = 0; n < DS; n++) Av[n] = -__expf(A_log[d * DS + n]);
    bool structured = (Av[0] < 0.f);
#pragma unroll
    for (int n = 1; n < DS; n++)
        structured = structured && (fabsf(Av[n] - (n + 1) * Av[0]) <= 1e-5f * fabsf(Av[n]));
    const float dsk = Dskip[d];
    __syncthreads();

    float h[DS];
    const size_t ho = ((size_t)((b * NCH + c) * DI) + d) * DS;
#pragma unroll
    for (int n = 0; n < DS; n++) h[n] = H0[ho + n];

    size_t p  = ((size_t)(b * LSEQ + l0)) * DI + d;
    size_t pz = ((size_t)(b * LSEQ + l0)) * (2 * DI) + DI + d;
    __nv_bfloat16 dq0 = delta[p],      uq0 = u[p],      zq0 = xz[pz];
    __nv_bfloat16 dq1 = delta[p + DI], uq1 = u[p + DI], zq1 = xz[pz + 2 * DI];

    for (int l = 0; l < CHL; l++, p += DI, pz += 2 * DI) {
        __nv_bfloat16 dq2 = __float2bfloat16(0.f), uq2 = dq2, zq2 = dq2;
        if (l + 2 < CHL) {
            dq2 = delta[p + 2 * DI];
            uq2 = u[p + 2 * DI];
            zq2 = xz[pz + 4 * DI];
        }
        const float dv = __bfloat162float(dq0);
        const float uv = __bfloat162float(uq0);
        const float zv = __bfloat162float(zq0);
        const float cv = dv * uv;
        float pw[DS];
        if (structured) {
            powers16(__expf(dv * Av[0]), pw);
        } else {
#pragma unroll
            for (int n = 0; n < DS; n++) pw[n] = __expf(dv * Av[n]);
        }
        float y0 = 0.f, y1 = 0.f, y2 = 0.f, y3 = 0.f;
#pragma unroll
        for (int n = 0; n < DS; n += 4) {
            h[n]     = fmaf(pw[n],     h[n],     cv * Bs[l * DS + n]);
            h[n + 1] = fmaf(pw[n + 1], h[n + 1], cv * Bs[l * DS + n + 1]);
            h[n + 2] = fmaf(pw[n + 2], h[n + 2], cv * Bs[l * DS + n + 2]);
            h[n + 3] = fmaf(pw[n + 3], h[n + 3], cv * Bs[l * DS + n + 3]);
            y0 = fmaf(h[n],     Cs[l * DS + n],     y0);
            y1 = fmaf(h[n + 1], Cs[l * DS + n + 1], y1);
            y2 = fmaf(h[n + 2], Cs[l * DS + n + 2], y2);
            y3 = fmaf(h[n + 3], Cs[l * DS + n + 3], y3);
        }
        const float y = (y0 + y1) + (y2 + y3) + uv * dsk;
        const float sig = 1.f / (1.f + __expf(-zv));
        yg[p] = __float2bfloat16(y * (zv * sig));
        dq0 = dq1; uq0 = uq1; zq0 = zq1;
        dq1 = dq2; uq1 = uq2; zq1 = zq2;
    }
}

// ---------------- launch ----------------
extern "C" void kernel_launch(void* const* d_in, const int* in_sizes, int n_in,
                              void* d_out, int out_size) {
    const float* x       = (const float*)d_in[0];
    const float* ln_g    = (const float*)d_in[1];
    const float* ln_b    = (const float*)d_in[2];
    const float* W_in    = (const float*)d_in[3];
    const float* conv_w  = (const float*)d_in[4];
    const float* conv_b  = (const float*)d_in[5];
    const float* W_xproj = (const float*)d_in[6];
    const float* W_dt    = (const float*)d_in[7];
    const float* b_dt    = (const float*)d_in[8];
    const float* A_log   = (const float*)d_in[9];
    const float* D_skip  = (const float*)d_in[10];
    const float* W_out   = (const float*)d_in[11];
    float* out = (float*)d_out;

    __nv_bfloat16 *xn, *xzbf, *ubf, *dtbf, *delbf, *yg, *wtin, *wtout, *wtxp, *wtdt;
    float *part, *xdbl, *Sb, *H0b, *dsumb;
    cudaGetSymbolAddress((void**)&xn,    g_xn_bf);
    cudaGetSymbolAddress((void**)&xzbf,  g_xz_bf);
    cudaGetSymbolAddress((void**)&ubf,   g_u_bf);
    cudaGetSymbolAddress((void**)&part,  g_part);
    cudaGetSymbolAddress((void**)&xdbl,  g_xdbl);
    cudaGetSymbolAddress((void**)&dtbf,  g_dt_bf);
    cudaGetSymbolAddress((void**)&delbf, g_del_bf);
    cudaGetSymbolAddress((void**)&yg,    g_yg_bf);
    cudaGetSymbolAddress((void**)&Sb,    g_S);
    cudaGetSymbolAddress((void**)&H0b,   g_H0);
    cudaGetSymbolAddress((void**)&dsumb, g_dsum);
    cudaGetSymbolAddress((void**)&wtin,  g_wt_in);
    cudaGetSymbolAddress((void**)&wtout, g_wt_out);
    cudaGetSymbolAddress((void**)&wtxp,  g_wt_xp);
    cudaGetSymbolAddress((void**)&wtdt,  g_wt_dt);

    const int smemBytes = 3 * 2 * 128 * 128;   // 98304
    cudaFuncSetAttribute(mma_gemm_kernel<0, true>,  cudaFuncAttributeMaxDynamicSharedMemorySize, smemBytes);
    cudaFuncSetAttribute(mma_gemm_kernel<0, false>, cudaFuncAttributeMaxDynamicSharedMemorySize, smemBytes);
    cudaFuncSetAttribute(mma_gemm_kernel<1, true>,  cudaFuncAttributeMaxDynamicSharedMemorySize, smemBytes);
    cudaFuncSetAttribute(mma_gemm_kernel<2, false>, cudaFuncAttributeMaxDynamicSharedMemorySize, smemBytes);

    // 1) prep
    prep_kernel<<<3264 + BL, dim3(32, 8)>>>(x, ln_g, ln_b, W_in, W_out, W_xproj, W_dt,
                                            xn, wtin, wtout, wtxp, wtdt);
    // 2) xz = xn @ W_in -> bf16
    mma_gemm_kernel<0, true><<<dim3((2 * DI) / 128, BL / 128, 1), 256, smemBytes>>>(
        xn, wtin, xzbf, BL, 2 * DI, DM, DM, 2 * DI, nullptr, DM, 0);
    // 3) conv + silu (sliding window, 4 timesteps/thread)
    conv_silu_kernel<<<((size_t)(BL / 4) * (DI / 8)) / 256, 256>>>(xzbf, conv_w, conv_b, ubf);
    // 4) x_dbl partials (split-K)  (PROFILED)
    mma_gemm_kernel<0, false><<<dim3(GP / 128, BL / 128, SPLITK), 256, smemBytes>>>(
        ubf, wtxp, part, BL, GP, DI, DI, GP, nullptr, DI / SPLITK, (size_t)BL * GP);
    // 5) reduce
    reduce_xdbl_kernel<<<(BL * GP / 4) / 256, 256>>>(part, xdbl, dtbf);
    // 6) delta = softplus(dt @ W_dt + b_dt) -> bf16
    mma_gemm_kernel<1, true><<<dim3(DI / 128, BL / 128, 1), 256, smemBytes>>>(
        dtbf, wtdt, delbf, BL, DI, RANK, RANK, DI, b_dt, RANK, 0);
    // 7-9) chunked selective scan (R8 geometry, NCH=16)
    scanA_kernel<<<dim3(DI / 128, NCH, BATCH), 128>>>(delbf, ubf, xdbl, A_log, Sb, dsumb);
    scanB_kernel<<<(BATCH * DI * DS) / 256, 256>>>(Sb, dsumb, A_log, H0b);
    scanC_kernel<<<dim3(DI / 128, NCH, BATCH), 128>>>(delbf, ubf, xdbl, xzbf,
                                                      A_log, D_skip, H0b, yg);
    // 10) out = x + yg @ W_out
    mma_gemm_kernel<2, false><<<dim3(DM / 128, BL / 128, 1), 256, smemBytes>>>(
        yg, wtout, out, BL, DM, DI, DI, DM, x, DI, 0);
}

// round 12
// speedup vs baseline: 1.5286x; 1.0862x over previous
#include <cuda_runtime.h>
#include <cuda_bf16.h>
#include <math.h>
#include <stdint.h>

// ---------------- problem constants ----------------
#define BATCH   2
#define LSEQ    2048
#define DM      1024
#define DI      2048
#define DS      16
#define DC      4
#define RANK    64
#define GDIM    96
#define GP      128
#define BL      (BATCH*LSEQ)  // 4096
#define SPLITK  4
#define NCH     32
#define CHL     (LSEQ/NCH)    // 64

// ---------------- scratch ----------------
__device__ __nv_bfloat16 g_xn_bf  [(size_t)BL*DM];
__device__ __nv_bfloat16 g_xz_bf  [(size_t)BL*2*DI];
__device__ __nv_bfloat16 g_u_bf   [(size_t)BL*DI];
__device__ float         g_part   [(size_t)SPLITK*BL*GP];
__device__ float         g_xdbl   [(size_t)BL*GP];
__device__ __nv_bfloat16 g_dt_bf  [(size_t)BL*RANK];
__device__ __nv_bfloat16 g_del_bf [(size_t)BL*DI];
__device__ __nv_bfloat16 g_yg_bf  [(size_t)BL*DI];
__device__ float         g_S      [(size_t)BATCH*NCH*DI*DS];
__device__ float         g_H0     [(size_t)BATCH*NCH*DI*DS];
__device__ float         g_dsum   [(size_t)BATCH*NCH*DI];
__device__ __nv_bfloat16 g_wt_in  [(size_t)(2*DI)*DM];
__device__ __nv_bfloat16 g_wt_out [(size_t)DM*DI];
__device__ __nv_bfloat16 g_wt_xp  [(size_t)GP*DI];
__device__ __nv_bfloat16 g_wt_dt  [(size_t)DI*RANK];

// ---------------- helpers ----------------
__device__ __forceinline__ uint32_t smem_u32(const void* p) {
    uint32_t a;
    asm("{ .reg .u64 t; cvta.to.shared.u64 t, %1; cvt.u32.u64 %0, t; }" : "=r"(a) : "l"(p));
    return a;
}
__device__ __forceinline__ void cp16(uint32_t dst, const void* src) {
    asm volatile("cp.async.cg.shared.global [%0], [%1], 16;" :: "r"(dst), "l"(src));
}
#define CP_COMMIT() asm volatile("cp.async.commit_group;")
#define CP_WAIT1()  asm volatile("cp.async.wait_group 1;")

__device__ __forceinline__ void mma_bf16(float* c, const uint32_t* a, const uint32_t* b) {
    asm volatile(
        "mma.sync.aligned.m16n8k16.row.col.f32.bf16.bf16.f32 "
        "{%0,%1,%2,%3}, {%4,%5,%6,%7}, {%8,%9}, {%0,%1,%2,%3};"
        : "+f"(c[0]), "+f"(c[1]), "+f"(c[2]), "+f"(c[3])
        : "r"(a[0]), "r"(a[1]), "r"(a[2]), "r"(a[3]), "r"(b[0]), "r"(b[1]));
}
#define LDSM4(r0, r1, r2, r3, addr) \
    asm volatile("ldmatrix.sync.aligned.m8n8.x4.shared.b16 {%0,%1,%2,%3}, [%4];" \
        : "=r"(r0), "=r"(r1), "=r"(r2), "=r"(r3) : "r"(addr))

__device__ __forceinline__ float softplus_f(float t) {
    return (t > 20.f) ? t : __logf(1.f + __expf(t));
}
__device__ __forceinline__ void powers16(float w, float* pw) {
    const float w2 = w * w, w4 = w2 * w2, w8 = w4 * w4;
    pw[0]  = w;        pw[1]  = w2;       pw[2]  = w2 * w;   pw[3]  = w4;
    pw[4]  = w4 * w;   pw[5]  = w4 * w2;  pw[6]  = w4 * pw[2]; pw[7] = w8;
    pw[8]  = w8 * w;   pw[9]  = w8 * w2;  pw[10] = w8 * pw[2]; pw[11] = w8 * w4;
    pw[12] = w8 * pw[4]; pw[13] = w8 * pw[5]; pw[14] = w8 * pw[6]; pw[15] = w8 * w8;
}

// ---------------- prep: all weight transposes + layernorm, one launch -------
__device__ __forceinline__ void transpose64(const float* in, __nv_bfloat16* out,
                                            int K, int Nsrc, int Nout,
                                            int kb, int nb, int tx, int ty,
                                            float (*t)[33]) {
#pragma unroll
    for (int r = ty; r < 64; r += 8) {
        const int n = nb + tx;
        t[r][tx] = (n < Nsrc) ? in[(size_t)(kb + r) * Nsrc + n] : 0.f;
    }
    __syncthreads();
#pragma unroll
    for (int j = ty; j < 32; j += 8) {
        const int n = nb + j;
        if (n < Nout) {
            const __nv_bfloat162 v = __floats2bfloat162_rn(t[tx * 2][j], t[tx * 2 + 1][j]);
            *(__nv_bfloat162*)(out + (size_t)n * K + kb + tx * 2) = v;
        }
    }
}

__global__ void prep_kernel(const float* __restrict__ x,
                            const float* __restrict__ gamma,
                            const float* __restrict__ beta,
                            const float* __restrict__ Win,
                            const float* __restrict__ Wout,
                            const float* __restrict__ Wxp,
                            const float* __restrict__ Wdt,
                            __nv_bfloat16* __restrict__ xn,
                            __nv_bfloat16* __restrict__ wtin,
                            __nv_bfloat16* __restrict__ wtout,
                            __nv_bfloat16* __restrict__ wtxp,
                            __nv_bfloat16* __restrict__ wtdt) {
    __shared__ float t[64][33];
    const int tx = threadIdx.x, ty = threadIdx.y;
    int b = blockIdx.x;
    if (b < 2048) {
        transpose64(Win, wtin, DM, 2 * DI, 2 * DI, (b & 15) * 64, (b >> 4) * 32, tx, ty, t);
    } else if (b < 3072) {
        b -= 2048;
        transpose64(Wout, wtout, DI, DM, DM, (b & 31) * 64, (b >> 5) * 32, tx, ty, t);
    } else if (b < 3200) {
        b -= 3072;
        transpose64(Wxp, wtxp, DI, GDIM, GP, (b & 31) * 64, (b >> 5) * 32, tx, ty, t);
    } else if (b < 3264) {
        b -= 3200;
        transpose64(Wdt, wtdt, RANK, DI, DI, 0, b * 32, tx, ty, t);
    } else {
        const int row = b - 3264;
        const int tid = ty * 32 + tx;
        const float4 v = ((const float4*)(x + (size_t)row * DM))[tid];
        float s  = v.x + v.y + v.z + v.w;
        float s2 = v.x * v.x + v.y * v.y + v.z * v.z + v.w * v.w;
#pragma unroll
        for (int o = 16; o > 0; o >>= 1) {
            s  += __shfl_xor_sync(0xffffffffu, s,  o);
            s2 += __shfl_xor_sync(0xffffffffu, s2, o);
        }
        if ((tid & 31) == 0) { t[0][tid >> 5] = s; t[1][tid >> 5] = s2; }
        __syncthreads();
        s = 0.f; s2 = 0.f;
#pragma unroll
        for (int i = 0; i < 8; i++) { s += t[0][i]; s2 += t[1][i]; }
        const float mean = s * (1.f / DM);
        const float var  = s2 * (1.f / DM) - mean * mean;
        const float rstd = rsqrtf(var + 1e-5f);
        const float4 gm = ((const float4*)gamma)[tid];
        const float4 bt = ((const float4*)beta)[tid];
        __nv_bfloat16* orow = xn + (size_t)row * DM + tid * 4;
        *(__nv_bfloat162*)(orow) =
            __floats2bfloat162_rn((v.x - mean) * rstd * gm.x + bt.x,
                                  (v.y - mean) * rstd * gm.y + bt.y);
        *(__nv_bfloat162*)(orow + 2) =
            __floats2bfloat162_rn((v.z - mean) * rstd * gm.z + bt.z,
                                  (v.w - mean) * rstd * gm.w + bt.w);
    }
}

// ---------------- conv + silu: 8 channels x 4 timesteps, sliding window -----
__global__ void conv_silu_kernel(const __nv_bfloat16* __restrict__ xz,
                                 const float* __restrict__ w,
                                 const float* __restrict__ bias,
                                 __nv_bfloat16* __restrict__ ubf) {
    const int idx = blockIdx.x * blockDim.x + threadIdx.x;  // (BL/4)*(DI/8)
    const int dg  = idx & 255;
    const int bq  = idx >> 8;
    const int bl0 = bq * 4;
    const int l0  = bl0 & (LSEQ - 1);
    const int d0  = dg << 3;

    float bv[8];
    {
        const float4 b0 = *(const float4*)(bias + d0);
        const float4 b1 = *(const float4*)(bias + d0 + 4);
        bv[0] = b0.x; bv[1] = b0.y; bv[2] = b0.z; bv[3] = b0.w;
        bv[4] = b1.x; bv[5] = b1.y; bv[6] = b1.z; bv[7] = b1.w;
    }
    float wv[4][8];
#pragma unroll
    for (int k = 0; k < 8; k++) {
        const float4 wk = *(const float4*)(w + (d0 + k) * 4);
        wv[0][k] = wk.x; wv[1][k] = wk.y; wv[2][k] = wk.z; wv[3][k] = wk.w;
    }

    auto load_row = [&](int bl, bool valid, float* r) {
        if (valid) {
            const uint4 q = *(const uint4*)(xz + (size_t)bl * (2 * DI) + d0);
            const __nv_bfloat162* h = (const __nv_bfloat162*)&q;
#pragma unroll
            for (int k2 = 0; k2 < 4; k2++) {
                const float2 f = __bfloat1622float2(h[k2]);
                r[k2 * 2] = f.x; r[k2 * 2 + 1] = f.y;
            }
        } else {
#pragma unroll
            for (int k = 0; k < 8; k++) r[k] = 0.f;
        }
    };

    float w0[8], w1[8], w2[8], w3[8];
    const bool interior = (l0 != 0);
    load_row(bl0 - 3, interior, w0);
    load_row(bl0 - 2, interior, w1);
    load_row(bl0 - 1, interior, w2);

#pragma unroll
    for (int t = 0; t < 4; t++) {
        load_row(bl0 + t, true, w3);
        uint4 oq;
        __nv_bfloat162* oh = (__nv_bfloat162*)&oq;
#pragma unroll
        for (int k2 = 0; k2 < 4; k2++) {
            float a0 = bv[k2 * 2], a1 = bv[k2 * 2 + 1];
            a0 = fmaf(wv[0][k2 * 2], w0[k2 * 2], a0);
            a1 = fmaf(wv[0][k2 * 2 + 1], w0[k2 * 2 + 1], a1);
            a0 = fmaf(wv[1][k2 * 2], w1[k2 * 2], a0);
            a1 = fmaf(wv[1][k2 * 2 + 1], w1[k2 * 2 + 1], a1);
            a0 = fmaf(wv[2][k2 * 2], w2[k2 * 2], a0);
            a1 = fmaf(wv[2][k2 * 2 + 1], w2[k2 * 2 + 1], a1);
            a0 = fmaf(wv[3][k2 * 2], w3[k2 * 2], a0);
            a1 = fmaf(wv[3][k2 * 2 + 1], w3[k2 * 2 + 1], a1);
            const float s0 = a0 / (1.f + __expf(-a0));
            const float s1 = a1 / (1.f + __expf(-a1));
            oh[k2] = __floats2bfloat162_rn(s0, s1);
        }
        *(uint4*)(ubf + (size_t)(bl0 + t) * DI + d0) = oq;
#pragma unroll
        for (int k = 0; k < 8; k++) { w0[k] = w1[k]; w1[k] = w2[k]; w2[k] = w3[k]; }
    }
}

// ---------------- bf16 mma.sync GEMM with ldmatrix (R8 proven) ----------------
template <int EPI, bool OBF>
__global__ __launch_bounds__(256, 2)
void mma_gemm_kernel(const __nv_bfloat16* __restrict__ A,
                     const __nv_bfloat16* __restrict__ Bt,
                     void* __restrict__ Cv, int M, int N,
                     int lda, int ldb, int ldc, const float* __restrict__ E,
                     int Kloc, size_t partStride) {
    constexpr int STAGE_BYTES = 2 * 128 * 128;
    constexpr int STAGES = 3;

    extern __shared__ __align__(128) char smem[];
    const uint32_t smem_b = smem_u32(smem);

    const int tid  = threadIdx.x;
    const int wid  = tid >> 5;
    const int lane = tid & 31;
    const int g    = lane >> 2;
    const int t    = lane & 3;
    const int rl   = lane & 7;
    const int l3   = (lane >> 3) & 1;
    const int l4   = lane >> 4;

    const int warpRow = wid & 1;
    const int warpCol = wid >> 1;
    const int rowBase = blockIdx.y * 128;
    const int colBase = blockIdx.x * 128;
    const int kbase   = blockIdx.z * Kloc;

    float acc[4][4][4];
#pragma unroll
    for (int i = 0; i < 4; i++)
#pragma unroll
        for (int j = 0; j < 4; j++)
#pragma unroll
            for (int q = 0; q < 4; q++) acc[i][j][q] = 0.f;

    const int nchunk = Kloc / 64;

    auto load_stage = [&](int kc, int s) {
        if (kc < nchunk) {
            const uint32_t base = smem_b + (uint32_t)s * STAGE_BYTES;
            const int rw = wid * 4 + (lane >> 3);
            const int un = lane & 7;
#pragma unroll
            for (int it = 0; it < 4; it++) {
                const int r = it * 32 + rw;
                const uint32_t sw = (uint32_t)((un ^ (r & 7)) << 4);
                cp16(base + (uint32_t)r * 128 + sw,
                     A + (size_t)(rowBase + r) * lda + kbase + kc * 64 + un * 8);
                cp16(base + 16384u + (uint32_t)r * 128 + sw,
                     Bt + (size_t)(colBase + r) * ldb + kbase + kc * 64 + un * 8);
            }
        }
        CP_COMMIT();
    };

    uint32_t rowOffA[4], colOffB[2];
#pragma unroll
    for (int mt = 0; mt < 4; mt++)
        rowOffA[mt] = (uint32_t)(warpRow * 64 + mt * 16 + l3 * 8 + rl) * 128;
#pragma unroll
    for (int n2 = 0; n2 < 2; n2++)
        colOffB[n2] = 16384u + (uint32_t)(warpCol * 32 + n2 * 16 + l4 * 8 + rl) * 128;

    load_stage(0, 0);
    load_stage(1, 1);

    int sidx = 0;
    for (int i = 0; i < nchunk; i++) {
        CP_WAIT1();
        __syncthreads();
        int snext = sidx + 2; if (snext >= STAGES) snext -= STAGES;
        load_stage(i + 2, snext);

        const uint32_t st = smem_b + (uint32_t)sidx * STAGE_BYTES;

#pragma unroll
        for (int ks = 0; ks < 4; ks++) {
            const uint32_t offA = (uint32_t)(((ks * 2 + l4) ^ rl) << 4);
            const uint32_t offB = (uint32_t)(((ks * 2 + l3) ^ rl) << 4);
            uint32_t afr[4][4], bfr[4][2];
#pragma unroll
            for (int mt = 0; mt < 4; mt++)
                LDSM4(afr[mt][0], afr[mt][1], afr[mt][2], afr[mt][3],
                      st + rowOffA[mt] + offA);
#pragma unroll
            for (int n2 = 0; n2 < 2; n2++)
                LDSM4(bfr[2 * n2][0], bfr[2 * n2][1], bfr[2 * n2 + 1][0], bfr[2 * n2 + 1][1],
                      st + colOffB[n2] + offB);
#pragma unroll
            for (int mt = 0; mt < 4; mt++)
#pragma unroll
                for (int nt = 0; nt < 4; nt++)
                    mma_bf16(acc[mt][nt], afr[mt], bfr[nt]);
        }
        sidx++; if (sidx >= STAGES) sidx -= STAGES;
    }

    const int rW = rowBase + warpRow * 64;
    const int cW = colBase + warpCol * 32;
#pragma unroll
    for (int mt = 0; mt < 4; mt++) {
#pragma unroll
        for (int nt = 0; nt < 4; nt++) {
            const int r0 = rW + mt * 16 + g;
            const int r1 = r0 + 8;
            const int c0 = cW + nt * 8 + 2 * t;
            float v0 = acc[mt][nt][0], v1 = acc[mt][nt][1];
            float v2 = acc[mt][nt][2], v3 = acc[mt][nt][3];
            if (EPI == 1) {
                const float b0 = E[c0], b1 = E[c0 + 1];
                v0 = softplus_f(v0 + b0);
                v1 = softplus_f(v1 + b1);
                v2 = softplus_f(v2 + b0);
                v3 = softplus_f(v3 + b1);
            } else if (EPI == 2) {
                const float2 e0 = *(const float2*)(E + (size_t)r0 * ldc + c0);
                const float2 e1 = *(const float2*)(E + (size_t)r1 * ldc + c0);
                v0 += e0.x; v1 += e0.y; v2 += e1.x; v3 += e1.y;
            }
            if (OBF) {
                __nv_bfloat16* C = (__nv_bfloat16*)Cv + (size_t)blockIdx.z * partStride;
                *(__nv_bfloat162*)(C + (size_t)r0 * ldc + c0) = __floats2bfloat162_rn(v0, v1);
                *(__nv_bfloat162*)(C + (size_t)r1 * ldc + c0) = __floats2bfloat162_rn(v2, v3);
            } else {
                float* C = (float*)Cv + (size_t)blockIdx.z * partStride;
                *(float2*)(C + (size_t)r0 * ldc + c0) = make_float2(v0, v1);
                *(float2*)(C + (size_t)r1 * ldc + c0) = make_float2(v2, v3);
            }
        }
    }
}

// ---------------- split-K reduce (float4) + dt->bf16 ----------------
__global__ void reduce_xdbl_kernel(const float* __restrict__ part,
                                   float* __restrict__ xdbl,
                                   __nv_bfloat16* __restrict__ dtbf) {
    const int i4 = blockIdx.x * blockDim.x + threadIdx.x;    // BL*GP/4
    const size_t S4 = (size_t)BL * GP / 4;
    const float4* p4 = (const float4*)part;
    const float4 a = p4[i4], b = p4[i4 + S4], c = p4[i4 + 2 * S4], d = p4[i4 + 3 * S4];
    float4 s;
    s.x = a.x + b.x + c.x + d.x;
    s.y = a.y + b.y + c.y + d.y;
    s.z = a.z + b.z + c.z + d.z;
    s.w = a.w + b.w + c.w + d.w;
    ((float4*)xdbl)[i4] = s;
    const int col = (i4 << 2) & (GP - 1);
    if (col < RANK) {
        const int row = i4 >> 5;
        __nv_bfloat16* dp = dtbf + (size_t)row * RANK + col;
        *(__nv_bfloat162*)(dp)     = __floats2bfloat162_rn(s.x, s.y);
        *(__nv_bfloat162*)(dp + 2) = __floats2bfloat162_rn(s.z, s.w);
    }
}

// ---------------- scan pass A (distance-4 prefetch, NCH=32) -----------------
__global__ void scanA_kernel(const __nv_bfloat16* __restrict__ delta,
                             const __nv_bfloat16* __restrict__ u,
                             const float* __restrict__ xdbl,
                             const float* __restrict__ A_log,
                             float* __restrict__ S, float* __restrict__ dsum) {
    __shared__ float Bs[CHL * DS];
    const int tid = threadIdx.x;
    const int d = blockIdx.x * 128 + tid;
    const int c = blockIdx.y, b = blockIdx.z;
    const int l0 = c * CHL;

    const float4* xd4 = (const float4*)xdbl;
    for (int i = tid; i < CHL * 4; i += 128) {
        const int l = i >> 2, q = i & 3;
        ((float4*)Bs)[i] = xd4[((size_t)(b * LSEQ + l0 + l)) * 32 + 16 + q];
    }

    float Av[DS];
#pragma unroll
    for (int n = 0; n < DS; n++) Av[n] = -__expf(A_log[d * DS + n]);
    bool structured = (Av[0] < 0.f);
#pragma unroll
    for (int n = 1; n < DS; n++)
        structured = structured && (fabsf(Av[n] - (n + 1) * Av[0]) <= 1e-5f * fabsf(Av[n]));
    __syncthreads();

    float h[DS];
#pragma unroll
    for (int n = 0; n < DS; n++) h[n] = 0.f;
    float ds = 0.f;

    const size_t pbase = ((size_t)(b * LSEQ + l0)) * DI + d;
    __nv_bfloat16 dq[4], uq[4];
#pragma unroll
    for (int j = 0; j < 4; j++) { dq[j] = delta[pbase + j * DI]; uq[j] = u[pbase + j * DI]; }

    for (int lb = 0; lb < CHL; lb += 4) {
#pragma unroll
        for (int j = 0; j < 4; j++) {
            const int l = lb + j;
            const float dv = __bfloat162float(dq[j]);
            const float uv = __bfloat162float(uq[j]);
            // prefetch l+4
            if (l + 4 < CHL) {
                dq[j] = delta[pbase + (size_t)(l + 4) * DI];
                uq[j] = u[pbase + (size_t)(l + 4) * DI];
            }
            ds += dv;
            const float cv = dv * uv;
            float pw[DS];
            if (structured) {
                powers16(__expf(dv * Av[0]), pw);
            } else {
#pragma unroll
                for (int n = 0; n < DS; n++) pw[n] = __expf(dv * Av[n]);
            }
#pragma unroll
            for (int n = 0; n < DS; n++)
                h[n] = fmaf(pw[n], h[n], cv * Bs[l * DS + n]);
        }
    }

    const size_t o = ((size_t)((b * NCH + c) * DI) + d) * DS;
#pragma unroll
    for (int n = 0; n < DS; n++) S[o + n] = h[n];
    dsum[(size_t)(b * NCH + c) * DI + d] = ds;
}

// ---------------- scan pass B ----------------
__global__ void scanB_kernel(const float* __restrict__ S,
                             const float* __restrict__ dsum,
                             const float* __restrict__ A_log,
                             float* __restrict__ H0) {
    const int idx = blockIdx.x * blockDim.x + threadIdx.x;
    const int n = idx & 15;
    const int d = (idx >> 4) & (DI - 1);
    const int b = idx >> 15;
    const float Av = -__expf(A_log[d * DS + n]);
    float h = 0.f;
#pragma unroll
    for (int c = 0; c < NCH; c++) {
        const size_t o = ((size_t)((b * NCH + c) * DI) + d) * DS + n;
        H0[o] = h;
        const float P = __expf(dsum[(size_t)(b * NCH + c) * DI + d] * Av);
        h = fmaf(P, h, S[o]);
    }
}

// ---------------- scan pass C (distance-4 prefetch, NCH=32) -----------------
__global__ void scanC_kernel(const __nv_bfloat16* __restrict__ delta,
                             const __nv_bfloat16* __restrict__ u,
                             const float* __restrict__ xdbl,
                             const __nv_bfloat16* __restrict__ xz,
                             const float* __restrict__ A_log,
                             const float* __restrict__ Dskip,
                             const float* __restrict__ H0,
                             __nv_bfloat16* __restrict__ yg) {
    __shared__ float Bs[CHL * DS];
    __shared__ float Cs[CHL * DS];
    const int tid = threadIdx.x;
    const int d = blockIdx.x * 128 + tid;
    const int c = blockIdx.y, b = blockIdx.z;
    const int l0 = c * CHL;

    const float4* xd4 = (const float4*)xdbl;
    for (int i = tid; i < CHL * 4; i += 128) {
        const int l = i >> 2, q = i & 3;
        const size_t row = ((size_t)(b * LSEQ + l0 + l)) * 32;
        ((float4*)Bs)[i] = xd4[row + 16 + q];
        ((float4*)Cs)[i] = xd4[row + 20 + q];
    }

    float Av[DS];
#pragma unroll
    for (int n = 0; n < DS; n++) Av[n] = -__expf(A_log[d * DS + n]);
    bool structured = (Av[0] < 0.f);
#pragma unroll
    for (int n = 1; n < DS; n++)
        structured = structured && (fabsf(Av[n] - (n + 1) * Av[0]) <= 1e-5f * fabsf(Av[n]));
    const float dsk = Dskip[d];
    __syncthreads();

    float h[DS];
    const size_t ho = ((size_t)((b * NCH + c) * DI) + d) * DS;
#pragma unroll
    for (int n = 0; n < DS; n++) h[n] = H0[ho + n];

    const size_t pbase  = ((size_t)(b * LSEQ + l0)) * DI + d;
    const size_t pzbase = ((size_t)(b * LSEQ + l0)) * (2 * DI) + DI + d;
    __nv_bfloat16 dq[4], uq[4], zq[4];
#pragma unroll
    for (int j = 0; j < 4; j++) {
        dq[j] = delta[pbase + j * DI];
        uq[j] = u[pbase + j * DI];
        zq[j] = xz[pzbase + (size_t)j * 2 * DI];
    }

    for (int lb = 0; lb < CHL; lb += 4) {
#pragma unroll
        for (int j = 0; j < 4; j++) {
            const int l = lb + j;
            const float dv = __bfloat162float(dq[j]);
            const float uv = __bfloat162float(uq[j]);
            const float zv = __bfloat162float(zq[j]);
            if (l + 4 < CHL) {
                dq[j] = delta[pbase + (size_t)(l + 4) * DI];
                uq[j] = u[pbase + (size_t)(l + 4) * DI];
                zq[j] = xz[pzbase + (size_t)(l + 4) * 2 * DI];
            }
            const float cv = dv * uv;
            float pw[DS];
            if (structured) {
                powers16(__expf(dv * Av[0]), pw);
            } else {
#pragma unroll
                for (int n = 0; n < DS; n++) pw[n] = __expf(dv * Av[n]);
            }
            float y0 = 0.f, y1 = 0.f, y2 = 0.f, y3 = 0.f;
#pragma unroll
            for (int n = 0; n < DS; n += 4) {
                h[n]     = fmaf(pw[n],     h[n],     cv * Bs[l * DS + n]);
                h[n + 1] = fmaf(pw[n + 1], h[n + 1], cv * Bs[l * DS + n + 1]);
                h[n + 2] = fmaf(pw[n + 2], h[n + 2], cv * Bs[l * DS + n + 2]);
                h[n + 3] = fmaf(pw[n + 3], h[n + 3], cv * Bs[l * DS + n + 3]);
                y0 = fmaf(h[n],     Cs[l * DS + n],     y0);
                y1 = fmaf(h[n + 1], Cs[l * DS + n + 1], y1);
                y2 = fmaf(h[n + 2], Cs[l * DS + n + 2], y2);
                y3 = fmaf(h[n + 3], Cs[l * DS + n + 3], y3);
            }
            const float y = (y0 + y1) + (y2 + y3) + uv * dsk;
            const float sig = 1.f / (1.f + __expf(-zv));
            yg[pbase + (size_t)l * DI] = __float2bfloat16(y * (zv * sig));
        }
    }
}

// ---------------- launch ----------------
extern "C" void kernel_launch(void* const* d_in, const int* in_sizes, int n_in,
                              void* d_out, int out_size) {
    const float* x       = (const float*)d_in[0];
    const float* ln_g    = (const float*)d_in[1];
    const float* ln_b    = (const float*)d_in[2];
    const float* W_in    = (const float*)d_in[3];
    const float* conv_w  = (const float*)d_in[4];
    const float* conv_b  = (const float*)d_in[5];
    const float* W_xproj = (const float*)d_in[6];
    const float* W_dt    = (const float*)d_in[7];
    const float* b_dt    = (const float*)d_in[8];
    const float* A_log   = (const float*)d_in[9];
    const float* D_skip  = (const float*)d_in[10];
    const float* W_out   = (const float*)d_in[11];
    float* out = (float*)d_out;

    __nv_bfloat16 *xn, *xzbf, *ubf, *dtbf, *delbf, *yg, *wtin, *wtout, *wtxp, *wtdt;
    float *part, *xdbl, *Sb, *H0b, *dsumb;
    cudaGetSymbolAddress((void**)&xn,    g_xn_bf);
    cudaGetSymbolAddress((void**)&xzbf,  g_xz_bf);
    cudaGetSymbolAddress((void**)&ubf,   g_u_bf);
    cudaGetSymbolAddress((void**)&part,  g_part);
    cudaGetSymbolAddress((void**)&xdbl,  g_xdbl);
    cudaGetSymbolAddress((void**)&dtbf,  g_dt_bf);
    cudaGetSymbolAddress((void**)&delbf, g_del_bf);
    cudaGetSymbolAddress((void**)&yg,    g_yg_bf);
    cudaGetSymbolAddress((void**)&Sb,    g_S);
    cudaGetSymbolAddress((void**)&H0b,   g_H0);
    cudaGetSymbolAddress((void**)&dsumb, g_dsum);
    cudaGetSymbolAddress((void**)&wtin,  g_wt_in);
    cudaGetSymbolAddress((void**)&wtout, g_wt_out);
    cudaGetSymbolAddress((void**)&wtxp,  g_wt_xp);
    cudaGetSymbolAddress((void**)&wtdt,  g_wt_dt);

    const int smemBytes = 3 * 2 * 128 * 128;   // 98304
    cudaFuncSetAttribute(mma_gemm_kernel<0, true>,  cudaFuncAttributeMaxDynamicSharedMemorySize, smemBytes);
    cudaFuncSetAttribute(mma_gemm_kernel<0, false>, cudaFuncAttributeMaxDynamicSharedMemorySize, smemBytes);
    cudaFuncSetAttribute(mma_gemm_kernel<1, true>,  cudaFuncAttributeMaxDynamicSharedMemorySize, smemBytes);
    cudaFuncSetAttribute(mma_gemm_kernel<2, false>, cudaFuncAttributeMaxDynamicSharedMemorySize, smemBytes);

    // 1) prep
    prep_kernel<<<3264 + BL, dim3(32, 8)>>>(x, ln_g, ln_b, W_in, W_out, W_xproj, W_dt,
                                            xn, wtin, wtout, wtxp, wtdt);
    // 2) xz = xn @ W_in -> bf16
    mma_gemm_kernel<0, true><<<dim3((2 * DI) / 128, BL / 128, 1), 256, smemBytes>>>(
        xn, wtin, xzbf, BL, 2 * DI, DM, DM, 2 * DI, nullptr, DM, 0);
    // 3) conv + silu (sliding window)
    conv_silu_kernel<<<((size_t)(BL / 4) * (DI / 8)) / 256, 256>>>(xzbf, conv_w, conv_b, ubf);
    // 4) x_dbl partials (split-K)  (PROFILED)
    mma_gemm_kernel<0, false><<<dim3(GP / 128, BL / 128, SPLITK), 256, smemBytes>>>(
        ubf, wtxp, part, BL, GP, DI, DI, GP, nullptr, DI / SPLITK, (size_t)BL * GP);
    // 5) reduce
    reduce_xdbl_kernel<<<(BL * GP / 4) / 256, 256>>>(part, xdbl, dtbf);
    // 6) delta = softplus(dt @ W_dt + b_dt) -> bf16
    mma_gemm_kernel<1, true><<<dim3(DI / 128, BL / 128, 1), 256, smemBytes>>>(
        dtbf, wtdt, delbf, BL, DI, RANK, RANK, DI, b_dt, RANK, 0);
    // 7-9) chunked selective scan (NCH=32, prefetch-4)
    scanA_kernel<<<dim3(DI / 128, NCH, BATCH), 128>>>(delbf, ubf, xdbl, A_log, Sb, dsumb);
    scanB_kernel<<<(BATCH * DI * DS) / 256, 256>>>(Sb, dsumb, A_log, H0b);
    scanC_kernel<<<dim3(DI / 128, NCH, BATCH), 128>>>(delbf, ubf, xdbl, xzbf,
                                                      A_log, D_skip, H0b, yg);
    // 10) out = x + yg @ W_out
    mma_gemm_kernel<2, false><<<dim3(DM / 128, BL / 128, 1), 256, smemBytes>>>(
        yg, wtout, out, BL, DM, DI, DI, DM, x, DI, 0);
}